// round 10
// baseline (speedup 1.0000x reference)
#include <cuda_runtime.h>
#include <cuda_bf16.h>
#include <math.h>
#include <stdint.h>

// Problem constants
#define BB 2
#define SS 2048
#define DD 1024
#define HH 16
#define HD 64
#define LL 4
#define MROWS (BB*SS)          // 4096
#define FOURD (4*DD)           // 4096

// ---------------------------------------------------------------------------
// Scratch (device globals; no allocation allowed)
// ---------------------------------------------------------------------------
__device__ float g_h[MROWS * DD];        // hidden state
__device__ float g_u[MROWS * DD];        // silu(u)
__device__ float g_attn[MROWS * DD];     // attention output
__device__ float g_cs[MROWS * 32];       // rope cos table (per token x 32 freqs)
__device__ float g_sn[MROWS * 32];       // rope sin table

__device__ __nv_bfloat16 g_wqk_hi[LL * FOURD * DD];  // uvqk_w^T split, [L][N=4D][K=D]
__device__ __nv_bfloat16 g_wqk_lo[LL * FOURD * DD];
__device__ __nv_bfloat16 g_wo_hi[LL * DD * DD];      // out_w^T split, [L][N=D][K=D]
__device__ __nv_bfloat16 g_wo_lo[LL * DD * DD];
__device__ __nv_bfloat16 g_ahi[MROWS * DD];          // h split (GEMM A input)
__device__ __nv_bfloat16 g_alo[MROWS * DD];
__device__ __nv_bfloat16 g_ghi[MROWS * DD];          // gated split (GEMM A input)
__device__ __nv_bfloat16 g_glo[MROWS * DD];
// q/k/v splits in [b,h,s,d] layout
__device__ __nv_bfloat16 g_qhi[MROWS * DD];
__device__ __nv_bfloat16 g_qlo[MROWS * DD];
__device__ __nv_bfloat16 g_khi[MROWS * DD];
__device__ __nv_bfloat16 g_klo[MROWS * DD];
__device__ __nv_bfloat16 g_vhi[MROWS * DD];
__device__ __nv_bfloat16 g_vlo[MROWS * DD];

// ---------------------------------------------------------------------------
// PTX helpers (legacy tensor-core path: valid under compute_103 PTX)
// ---------------------------------------------------------------------------
__device__ __forceinline__ uint32_t smem_u32(const void* p) {
    uint32_t a;
    asm("{ .reg .u64 t; cvta.to.shared.u64 t, %1; cvt.u32.u64 %0, t; }" : "=r"(a) : "l"(p));
    return a;
}
__device__ __forceinline__ void cp_async16(uint32_t dst, const void* src) {
    asm volatile("cp.async.cg.shared.global [%0], [%1], 16;" :: "r"(dst), "l"(src) : "memory");
}
#define CP_COMMIT()  asm volatile("cp.async.commit_group;" ::: "memory")
#define CP_WAIT0()   asm volatile("cp.async.wait_group 0;" ::: "memory")
#define CP_WAIT1()   asm volatile("cp.async.wait_group 1;" ::: "memory")

__device__ __forceinline__ void ldsm4(uint32_t* r, uint32_t addr) {
    asm volatile("ldmatrix.sync.aligned.m8n8.x4.shared.b16 {%0,%1,%2,%3}, [%4];"
                 : "=r"(r[0]), "=r"(r[1]), "=r"(r[2]), "=r"(r[3]) : "r"(addr));
}
__device__ __forceinline__ void ldsm4t(uint32_t* r, uint32_t addr) {
    asm volatile("ldmatrix.sync.aligned.m8n8.x4.trans.shared.b16 {%0,%1,%2,%3}, [%4];"
                 : "=r"(r[0]), "=r"(r[1]), "=r"(r[2]), "=r"(r[3]) : "r"(addr));
}
__device__ __forceinline__ void mma_bf16(float* c, const uint32_t* a, const uint32_t* b) {
    asm volatile("mma.sync.aligned.m16n8k16.row.col.f32.bf16.bf16.f32 "
                 "{%0,%1,%2,%3}, {%4,%5,%6,%7}, {%8,%9}, {%0,%1,%2,%3};"
                 : "+f"(c[0]), "+f"(c[1]), "+f"(c[2]), "+f"(c[3])
                 : "r"(a[0]), "r"(a[1]), "r"(a[2]), "r"(a[3]), "r"(b[0]), "r"(b[1]));
}
// pack two fp32 into bf16x2 reg: lo goes to bits[15:0]
__device__ __forceinline__ uint32_t packbf(float lo, float hi) {
    uint32_t r;
    asm("cvt.rn.bf16x2.f32 %0, %1, %2;" : "=r"(r) : "f"(hi), "f"(lo));
    return r;
}
// split two fp32 into bf16 hi/lo pairs and store as bf16x2
__device__ __forceinline__ void split_store2(__nv_bfloat16* hi, __nv_bfloat16* lo,
                                             size_t off, float x, float y) {
    __nv_bfloat162 h, l;
    h.x = __float2bfloat16(x);
    h.y = __float2bfloat16(y);
    l.x = __float2bfloat16(x - __bfloat162float(h.x));
    l.y = __float2bfloat16(y - __bfloat162float(h.y));
    *reinterpret_cast<__nv_bfloat162*>(hi + off) = h;
    *reinterpret_cast<__nv_bfloat162*>(lo + off) = l;
}

// ---------------------------------------------------------------------------
// Weight convert+transpose+split: W[K,N] fp32 -> Thi/Tlo [N,K] bf16 (layer z)
// ---------------------------------------------------------------------------
__global__ void wconv_k(const float* __restrict__ W, __nv_bfloat16* __restrict__ Thi,
                        __nv_bfloat16* __restrict__ Tlo, int K, int N) {
    __shared__ float t[32][33];
    int l = blockIdx.z;
    const float* Wl = W + (size_t)l * K * N;
    __nv_bfloat16* Hl = Thi + (size_t)l * K * N;
    __nv_bfloat16* Ll = Tlo + (size_t)l * K * N;
    int n0 = blockIdx.x * 32, k0 = blockIdx.y * 32;
    int tx = threadIdx.x, ty = threadIdx.y;
    #pragma unroll
    for (int i = 0; i < 32; i += 8)
        t[ty + i][tx] = Wl[(size_t)(k0 + ty + i) * N + n0 + tx];
    __syncthreads();
    #pragma unroll
    for (int i = 0; i < 32; i += 8) {
        float v = t[tx][ty + i];
        __nv_bfloat16 hi = __float2bfloat16(v);
        __nv_bfloat16 lo = __float2bfloat16(v - __bfloat162float(hi));
        size_t o = (size_t)(n0 + ty + i) * K + k0 + tx;
        Hl[o] = hi;
        Ll[o] = lo;
    }
}

// ---------------------------------------------------------------------------
// RoPE cos/sin table: per token, 32 freqs (layer-invariant, computed once)
// ---------------------------------------------------------------------------
__global__ void costab_k(const float* __restrict__ td, const int* __restrict__ pos,
                         float* __restrict__ cs, float* __restrict__ sn) {
    int idx = blockIdx.x * blockDim.x + threadIdx.x;   // MROWS*32
    int t = idx >> 5, i = idx & 31;
    float p = (float)pos[t] + 0.1f * logf(td[t] + 1.0f);
    float invf = expf(-logf(10000.0f) * (float)i / 32.0f);
    float f = p * invf;
    cs[idx] = cosf(f);
    sn[idx] = sinf(f);
}

// ---------------------------------------------------------------------------
// mma.sync bf16x3 GEMM: C = Ahi*Bhi + Ahi*Blo + Alo*Bhi (+bias, epilogues)
// CTA tile 128x256, BK=32, 8 warps @ 64x64 (2M x 4N), double-buffer cp.async.
// EPI 0: C = acc+bias+res               (out-proj, last layer)
// EPI 1: EPI0 + bf16 hi/lo split of C   (out-proj, feeds next uvqk GEMM)
// EPI 2: fused uvqk epilogue: silu(u)->u buf; v split; q,k rope+split [b,h,s,d]
// ---------------------------------------------------------------------------
#define ROWB 80                  // bytes per smem row (64B data + 16B pad)
#define A_B (128 * ROWB)         // 10240 B per A array (128 rows)
#define B_B (256 * ROWB)         // 20480 B per B array (256 rows)
#define STG_B (2 * A_B + 2 * B_B)  // 61440 B per stage
#define GSMEM (2 * STG_B)        // 122880 B

template<int EPI>
__global__ __launch_bounds__(256, 1)
void mmagemm_k(int N, int K,
               const __nv_bfloat16* __restrict__ Ahi, const __nv_bfloat16* __restrict__ Alo,
               const __nv_bfloat16* __restrict__ Bhi, const __nv_bfloat16* __restrict__ Blo,
               const float* __restrict__ bias, const float* __restrict__ res,
               float* __restrict__ C,
               __nv_bfloat16* __restrict__ Chi, __nv_bfloat16* __restrict__ Clo,
               float* __restrict__ u,
               __nv_bfloat16* __restrict__ qhi, __nv_bfloat16* __restrict__ qlo,
               __nv_bfloat16* __restrict__ khi, __nv_bfloat16* __restrict__ klo,
               __nv_bfloat16* __restrict__ vhi, __nv_bfloat16* __restrict__ vlo,
               const float* __restrict__ cstab, const float* __restrict__ sntab) {
    extern __shared__ char dynsm[];
    const uint32_t sb = smem_u32(dynsm);
    const int tid = threadIdx.x;
    const int lane = tid & 31, wid = tid >> 5;
    const int warpM = (wid & 1) * 64;    // 0 or 64
    const int warpN = (wid >> 1) * 64;   // 0..192
    const int m0 = blockIdx.y * 128;
    const int n0 = blockIdx.x * 256;
    const int nk = K / 32;

    const __nv_bfloat16* Asrc[2] = { Ahi + (size_t)m0 * K, Alo + (size_t)m0 * K };
    const __nv_bfloat16* Bsrc[2] = { Bhi + (size_t)n0 * K, Blo + (size_t)n0 * K };

    auto load_stage = [&](int stage, int kc) {
        const int k0 = kc * 32;
        const uint32_t dbase = sb + stage * STG_B;
        #pragma unroll
        for (int j = 0; j < 12; j++) {
            int idx = tid + 256 * j;           // 0..3071
            int rg = idx >> 2;                 // 0..767
            int ch = idx & 3;
            uint32_t dst;
            const __nv_bfloat16* src;
            if (rg < 256) {
                int arr = rg >> 7, row = rg & 127;
                src = Asrc[arr] + (size_t)row * K + k0 + ch * 8;
                dst = dbase + arr * A_B + row * ROWB + ch * 16;
            } else {
                int rgb = rg - 256;
                int arr = rgb >> 8, row = rgb & 255;
                src = Bsrc[arr] + (size_t)row * K + k0 + ch * 8;
                dst = dbase + 2 * A_B + arr * B_B + row * ROWB + ch * 16;
            }
            cp_async16(dst, src);
        }
        CP_COMMIT();
    };

    const uint32_t aoff = (uint32_t)(warpM + (lane & 15)) * ROWB + (lane >> 4) * 16;
    const uint32_t boff = (uint32_t)(warpN + (lane >> 4) * 8 + (lane & 7)) * ROWB
                          + ((lane >> 3) & 1) * 16;

    float acc[4][8][4] = {};

    load_stage(0, 0);

    for (int kc = 0; kc < nk; kc++) {
        if (kc + 1 < nk) {
            load_stage((kc + 1) & 1, kc + 1);
            CP_WAIT1();
        } else {
            CP_WAIT0();
        }
        __syncthreads();

        const uint32_t stb = sb + (kc & 1) * STG_B;
        #pragma unroll
        for (int ks = 0; ks < 2; ks++) {
            const uint32_t ko = ks * 32;
            uint32_t ah[4][4], al[4][4];
            #pragma unroll
            for (int mt = 0; mt < 4; mt++) {
                uint32_t a = stb + aoff + mt * (16 * ROWB) + ko;
                ldsm4(ah[mt], a);
                ldsm4(al[mt], a + A_B);
            }
            #pragma unroll
            for (int p = 0; p < 4; p++) {
                uint32_t bh[4], bl[4];
                uint32_t b = stb + 2 * A_B + boff + p * (16 * ROWB) + ko;
                ldsm4(bh, b);
                ldsm4(bl, b + B_B);
                #pragma unroll
                for (int mt = 0; mt < 4; mt++) {
                    #pragma unroll
                    for (int half = 0; half < 2; half++) {
                        float* c = acc[mt][2 * p + half];
                        mma_bf16(c, ah[mt], &bh[half * 2]);
                        mma_bf16(c, ah[mt], &bl[half * 2]);
                        mma_bf16(c, al[mt], &bh[half * 2]);
                    }
                }
            }
        }
        __syncthreads();
    }

    const int frow = lane >> 2;
    const int fcol = (lane & 3) * 2;

    if (EPI == 2) {
        // ---- fused uvqk epilogue ----
        const int gcol0 = n0 + warpN;              // head-aligned (64)
        const int region = gcol0 >> 10;            // 0=u 1=v 2=q 3=k
        const int hh = (gcol0 & 1023) >> 6;        // head index
        #pragma unroll
        for (int mt = 0; mt < 4; mt++) {
            const int mr0 = m0 + warpM + mt * 16 + frow;
            const int mr1 = mr0 + 8;
            const int b0 = mr0 >> 11, s0 = mr0 & (SS - 1);
            const int b1 = mr1 >> 11, s1 = mr1 & (SS - 1);
            const size_t ob0 = ((size_t)(b0 * HH + hh) * SS + s0) * HD;
            const size_t ob1 = ((size_t)(b1 * HH + hh) * SS + s1) * HD;
            if (region == 0) {
                #pragma unroll
                for (int nt = 0; nt < 8; nt++) {
                    const int n = gcol0 + nt * 8 + fcol;
                    const float* a = acc[mt][nt];
                    float2 bv = *reinterpret_cast<const float2*>(bias + n);
                    float x0 = a[0] + bv.x, y0 = a[1] + bv.y;
                    float x1 = a[2] + bv.x, y1 = a[3] + bv.y;
                    x0 = x0 / (1.0f + __expf(-x0));
                    y0 = y0 / (1.0f + __expf(-y0));
                    x1 = x1 / (1.0f + __expf(-x1));
                    y1 = y1 / (1.0f + __expf(-y1));
                    *reinterpret_cast<float2*>(u + (size_t)mr0 * DD + n) = make_float2(x0, y0);
                    *reinterpret_cast<float2*>(u + (size_t)mr1 * DD + n) = make_float2(x1, y1);
                }
            } else if (region == 1) {
                #pragma unroll
                for (int nt = 0; nt < 8; nt++) {
                    const int d0 = nt * 8 + fcol;
                    const int n = gcol0 + d0;
                    const float* a = acc[mt][nt];
                    float2 bv = *reinterpret_cast<const float2*>(bias + n);
                    split_store2(vhi, vlo, ob0 + d0, a[0] + bv.x, a[1] + bv.y);
                    split_store2(vhi, vlo, ob1 + d0, a[2] + bv.x, a[3] + bv.y);
                }
            } else {
                __nv_bfloat16* dhi = (region == 2) ? qhi : khi;
                __nv_bfloat16* dlo = (region == 2) ? qlo : klo;
                #pragma unroll
                for (int nt = 0; nt < 4; nt++) {
                    const int d0 = nt * 8 + fcol;          // 0..30
                    const int n = gcol0 + d0;
                    const float* a1 = acc[mt][nt];         // cols d0, d0+1
                    const float* a2 = acc[mt][nt + 4];     // cols d0+32, d0+33
                    float2 bv1 = *reinterpret_cast<const float2*>(bias + n);
                    float2 bv2 = *reinterpret_cast<const float2*>(bias + n + 32);
                    // row mr0
                    {
                        float2 c2 = *reinterpret_cast<const float2*>(cstab + (size_t)mr0 * 32 + d0);
                        float2 s2 = *reinterpret_cast<const float2*>(sntab + (size_t)mr0 * 32 + d0);
                        float q1a = a1[0] + bv1.x, q1b = a1[1] + bv1.y;
                        float q2a = a2[0] + bv2.x, q2b = a2[1] + bv2.y;
                        split_store2(dhi, dlo, ob0 + d0,
                                     q1a * c2.x - q2a * s2.x, q1b * c2.y - q2b * s2.y);
                        split_store2(dhi, dlo, ob0 + d0 + 32,
                                     q2a * c2.x + q1a * s2.x, q2b * c2.y + q1b * s2.y);
                    }
                    // row mr1
                    {
                        float2 c2 = *reinterpret_cast<const float2*>(cstab + (size_t)mr1 * 32 + d0);
                        float2 s2 = *reinterpret_cast<const float2*>(sntab + (size_t)mr1 * 32 + d0);
                        float q1a = a1[2] + bv1.x, q1b = a1[3] + bv1.y;
                        float q2a = a2[2] + bv2.x, q2b = a2[3] + bv2.y;
                        split_store2(dhi, dlo, ob1 + d0,
                                     q1a * c2.x - q2a * s2.x, q1b * c2.y - q2b * s2.y);
                        split_store2(dhi, dlo, ob1 + d0 + 32,
                                     q2a * c2.x + q1a * s2.x, q2b * c2.y + q1b * s2.y);
                    }
                }
            }
        }
    } else {
        // ---- out-proj epilogue: C = acc + bias + res (+ optional split) ----
        #pragma unroll
        for (int mt = 0; mt < 4; mt++) {
            const int m = m0 + warpM + mt * 16 + frow;
            #pragma unroll
            for (int nt = 0; nt < 8; nt++) {
                const int n = n0 + warpN + nt * 8 + fcol;
                const float* a = acc[mt][nt];
                float2 bv = *reinterpret_cast<const float2*>(bias + n);
                float2 r0 = *reinterpret_cast<const float2*>(res + (size_t)m * N + n);
                float2 r1 = *reinterpret_cast<const float2*>(res + (size_t)(m + 8) * N + n);
                float2 o0 = { a[0] + bv.x + r0.x, a[1] + bv.y + r0.y };
                float2 o1 = { a[2] + bv.x + r1.x, a[3] + bv.y + r1.y };
                *reinterpret_cast<float2*>(C + (size_t)m * N + n) = o0;
                *reinterpret_cast<float2*>(C + (size_t)(m + 8) * N + n) = o1;
                if (EPI == 1) {
                    split_store2(Chi, Clo, (size_t)m * N + n, o0.x, o0.y);
                    split_store2(Chi, Clo, (size_t)(m + 8) * N + n, o1.x, o1.y);
                }
            }
        }
    }
}

// ---------------------------------------------------------------------------
// block reduce (256 threads)
// ---------------------------------------------------------------------------
__device__ __forceinline__ float blockReduceSum(float v) {
    __shared__ float red[8];
    int lane = threadIdx.x & 31, wid = threadIdx.x >> 5;
    #pragma unroll
    for (int o = 16; o; o >>= 1) v += __shfl_down_sync(0xFFFFFFFFu, v, o);
    if (lane == 0) red[wid] = v;
    __syncthreads();
    float r = 0.f;
    if (threadIdx.x < 8) r = red[threadIdx.x];
    if (wid == 0) {
        #pragma unroll
        for (int o = 4; o; o >>= 1) r += __shfl_down_sync(0xFFFFFFFFu, r, o);
        if (lane == 0) red[0] = r;
    }
    __syncthreads();
    return red[0];
}

// RMS norm, vectorized: one row per 256-thread block (4 elems/thread).
template<bool SPLIT>
__global__ void rmsnorm_k(const float* __restrict__ in, const float* __restrict__ w,
                          float* __restrict__ out,
                          __nv_bfloat16* __restrict__ ohi, __nv_bfloat16* __restrict__ olo) {
    const int row = blockIdx.x, t = threadIdx.x;
    const size_t off = (size_t)row * DD + t * 4;
    float4 v = *reinterpret_cast<const float4*>(in + off);
    float ss = v.x * v.x + v.y * v.y + v.z * v.z + v.w * v.w;
    float tot = blockReduceSum(ss);
    float inv = rsqrtf(tot / (float)DD + 1e-6f);
    float4 wv = *reinterpret_cast<const float4*>(w + t * 4);
    float4 y = { v.x * wv.x * inv, v.y * wv.y * inv, v.z * wv.z * inv, v.w * wv.w * inv };
    *reinterpret_cast<float4*>(out + off) = y;
    if (SPLIT) {
        split_store2(ohi, olo, off, y.x, y.y);
        split_store2(ohi, olo, off + 2, y.z, y.w);
    }
}

// gated = rms_norm(attn, gate_w) * u  -> bf16 hi/lo split only (vectorized)
__global__ void rmsgate_k(const float* __restrict__ attn, const float* __restrict__ gw,
                          const float* __restrict__ u,
                          __nv_bfloat16* __restrict__ ghi, __nv_bfloat16* __restrict__ glo) {
    const int row = blockIdx.x, t = threadIdx.x;
    const size_t off = (size_t)row * DD + t * 4;
    float4 v = *reinterpret_cast<const float4*>(attn + off);
    float ss = v.x * v.x + v.y * v.y + v.z * v.z + v.w * v.w;
    float tot = blockReduceSum(ss);
    float inv = rsqrtf(tot / (float)DD + 1e-6f);
    float4 wv = *reinterpret_cast<const float4*>(gw + t * 4);
    float4 uv = *reinterpret_cast<const float4*>(u + off);
    float y0 = v.x * wv.x * inv * uv.x;
    float y1 = v.y * wv.y * inv * uv.y;
    float y2 = v.z * wv.z * inv * uv.z;
    float y3 = v.w * wv.w * inv * uv.w;
    split_store2(ghi, glo, off, y0, y1);
    split_store2(ghi, glo, off + 2, y2, y3);
}

// ---------------------------------------------------------------------------
// Tensor-core causal SiLU attention, bf16x3.
// grid=(S/256, B*H), 256 threads (8 warps x 32 q-rows -> CTA 256 q-rows).
// K/V tiles 64 keys, 3-stage cp.async pipeline. W split in registers for PV.
// qt reversed (heavy diagonal CTAs first) for wave balance.
// ---------------------------------------------------------------------------
#define AROWB 144                 // 72 elems * 2B, 16B-aligned
#define QAB (256 * AROWB)         // 36864 B per Q array (256 rows)
#define KVA (64 * AROWB)          // 9216 B per KV array
#define KVSTG (4 * KVA)           // 36864 B per stage (khi,klo,vhi,vlo)
#define ATTN_SMEM (2 * QAB + 3 * KVSTG)   // 184320 B

__global__ __launch_bounds__(256, 1)
void attn_mma_k(const __nv_bfloat16* __restrict__ qhi, const __nv_bfloat16* __restrict__ qlo,
                const __nv_bfloat16* __restrict__ khi, const __nv_bfloat16* __restrict__ klo,
                const __nv_bfloat16* __restrict__ vhi, const __nv_bfloat16* __restrict__ vlo,
                float* __restrict__ out) {
    extern __shared__ char dynsm[];
    const uint32_t sb = smem_u32(dynsm);
    const int tid = threadIdx.x;
    const int lane = tid & 31, wid = tid >> 5;
    const int qt = gridDim.x - 1 - blockIdx.x;    // heavy tiles first
    const int bh = blockIdx.y;
    const int b = bh >> 4, h = bh & 15;
    const int q0 = qt * 256;
    const int nkt = 4 * qt + 4;

    const size_t hb = (size_t)bh * SS;

    // ---- load Q (hi/lo), 256 rows ----
    {
        const __nv_bfloat16* qsrc[2] = { qhi + (hb + q0) * HD, qlo + (hb + q0) * HD };
        #pragma unroll
        for (int j = 0; j < 16; j++) {
            int idx = tid + 256 * j;         // 0..4095
            int arr = idx >> 11, rem = idx & 2047;
            int row = rem >> 3, seg = rem & 7;
            cp_async16(sb + arr * QAB + row * AROWB + seg * 16,
                       qsrc[arr] + (size_t)row * HD + seg * 8);
        }
        CP_COMMIT();
    }

    const __nv_bfloat16* kvsrc[4] = { khi + hb * HD, klo + hb * HD,
                                      vhi + hb * HD, vlo + hb * HD };
    auto load_kv = [&](int stage, int kt) {
        const int k0 = kt * 64;
        const uint32_t dbase = sb + 2 * QAB + stage * KVSTG;
        #pragma unroll
        for (int j = 0; j < 8; j++) {
            int idx = tid + 256 * j;
            int arr = idx >> 9, rem = idx & 511;
            int row = rem >> 3, seg = rem & 7;
            cp_async16(dbase + arr * KVA + row * AROWB + seg * 16,
                       kvsrc[arr] + (size_t)(k0 + row) * HD + seg * 8);
        }
        CP_COMMIT();
    };

    load_kv(0, 0);
    load_kv(1, 1);

    // fragment offsets: warp covers q rows [wid*32, wid*32+32)
    const uint32_t aoff = (uint32_t)(wid * 32 + (lane & 15)) * AROWB + (lane >> 4) * 16;
    const uint32_t boff = (uint32_t)((lane >> 4) * 8 + (lane & 7)) * AROWB + ((lane >> 3) & 1) * 16;
    const uint32_t voff = (uint32_t)(((lane >> 3) & 1) * 8 + (lane & 7)) * AROWB + (lane >> 4) * 16;

    const int wrow0 = q0 + wid * 32;             // warp's first q row
    const int rlane = lane >> 2;                 // fragment row within 8
    float o[2][8][4] = {};

    for (int kt = 0; kt < nkt; kt++) {
        if (kt + 1 < nkt) { CP_WAIT1(); } else { CP_WAIT0(); }
        __syncthreads();

        const int k0 = kt * 64;
        const uint32_t kb = sb + 2 * QAB + (kt % 3) * KVSTG;

        if (k0 <= wrow0 + 31) {   // not fully masked for this warp
            // ---- S = Q K^T (bf16x3): 32 q-rows x 64 keys ----
            float s[2][8][4] = {};
            #pragma unroll
            for (int ks = 0; ks < 4; ks++) {
                uint32_t aH[2][4], aL[2][4];
                #pragma unroll
                for (int mt = 0; mt < 2; mt++) {
                    uint32_t a = sb + aoff + mt * (16 * AROWB) + ks * 32;
                    ldsm4(aH[mt], a);
                    ldsm4(aL[mt], a + QAB);
                }
                #pragma unroll
                for (int p = 0; p < 4; p++) {
                    uint32_t bH[4], bL[4];
                    uint32_t ba = kb + boff + p * (16 * AROWB) + ks * 32;
                    ldsm4(bH, ba);
                    ldsm4(bL, ba + KVA);
                    #pragma unroll
                    for (int mt = 0; mt < 2; mt++) {
                        #pragma unroll
                        for (int half = 0; half < 2; half++) {
                            float* acc = s[mt][2 * p + half];
                            mma_bf16(acc, aH[mt], &bH[half * 2]);
                            mma_bf16(acc, aH[mt], &bL[half * 2]);
                            mma_bf16(acc, aL[mt], &bH[half * 2]);
                        }
                    }
                }
            }
            // ---- silu + causal mask ----
            const bool needmask = (k0 + 63 > wrow0);
            #pragma unroll
            for (int mt = 0; mt < 2; mt++) {
                #pragma unroll
                for (int n = 0; n < 8; n++) {
                    int col0 = k0 + 8 * n + (lane & 3) * 2;
                    #pragma unroll
                    for (int e = 0; e < 4; e++) {
                        int r = wrow0 + mt * 16 + rlane + ((e >> 1) ? 8 : 0);
                        int c = col0 + (e & 1);
                        float v = s[mt][n][e] * 0.125f;
                        v = v / (1.0f + __expf(-v));
                        if (needmask && c > r) v = 0.0f;
                        s[mt][n][e] = v;
                    }
                }
            }
            // ---- O += W V (bf16x3, W split in registers) ----
            #pragma unroll
            for (int kk = 0; kk < 4; kk++) {
                uint32_t wh[2][4], wl[2][4];
                #pragma unroll
                for (int mt = 0; mt < 2; mt++) {
                    const float* t0 = s[mt][2 * kk];
                    const float* t1 = s[mt][2 * kk + 1];
                    float h00 = __bfloat162float(__float2bfloat16(t0[0]));
                    float h01 = __bfloat162float(__float2bfloat16(t0[1]));
                    float h02 = __bfloat162float(__float2bfloat16(t0[2]));
                    float h03 = __bfloat162float(__float2bfloat16(t0[3]));
                    float h10 = __bfloat162float(__float2bfloat16(t1[0]));
                    float h11 = __bfloat162float(__float2bfloat16(t1[1]));
                    float h12 = __bfloat162float(__float2bfloat16(t1[2]));
                    float h13 = __bfloat162float(__float2bfloat16(t1[3]));
                    wh[mt][0] = packbf(h00, h01); wh[mt][1] = packbf(h02, h03);
                    wh[mt][2] = packbf(h10, h11); wh[mt][3] = packbf(h12, h13);
                    wl[mt][0] = packbf(t0[0] - h00, t0[1] - h01);
                    wl[mt][1] = packbf(t0[2] - h02, t0[3] - h03);
                    wl[mt][2] = packbf(t1[0] - h10, t1[1] - h11);
                    wl[mt][3] = packbf(t1[2] - h12, t1[3] - h13);
                }
                #pragma unroll
                for (int dg = 0; dg < 4; dg++) {
                    uint32_t va = kb + 2 * KVA + kk * (16 * AROWB) + voff + dg * 32;
                    uint32_t vH[4], vL[4];
                    ldsm4t(vH, va);
                    ldsm4t(vL, va + KVA);
                    #pragma unroll
                    for (int mt = 0; mt < 2; mt++) {
                        #pragma unroll
                        for (int half = 0; half < 2; half++) {
                            float* acc = o[mt][2 * dg + half];
                            mma_bf16(acc, wh[mt], &vH[half * 2]);
                            mma_bf16(acc, wh[mt], &vL[half * 2]);
                            mma_bf16(acc, wl[mt], &vH[half * 2]);
                        }
                    }
                }
            }
        }

        if (kt + 2 < nkt) load_kv((kt + 2) % 3, kt + 2);
    }

    // ---- write out [B,S,D] fp32: 32 rows x 64 cols per warp ----
    #pragma unroll
    for (int mt = 0; mt < 2; mt++) {
        const int row0 = wrow0 + mt * 16 + rlane;
        #pragma unroll
        for (int dt = 0; dt < 8; dt++) {
            int col = h * HD + dt * 8 + (lane & 3) * 2;
            *reinterpret_cast<float2*>(out + (size_t)(b * SS + row0) * DD + col) =
                make_float2(o[mt][dt][0], o[mt][dt][1]);
            *reinterpret_cast<float2*>(out + (size_t)(b * SS + row0 + 8) * DD + col) =
                make_float2(o[mt][dt][2], o[mt][dt][3]);
        }
    }
}

// ---------------------------------------------------------------------------
// kernel_launch
// ---------------------------------------------------------------------------
extern "C" void kernel_launch(void* const* d_in, const int* in_sizes, int n_in,
                              void* d_out, int out_size) {
    const float* x        = (const float*)d_in[0];
    const float* td       = (const float*)d_in[1];
    // d_in[2] = attn_mask: structurally tril(ones) -> causal mask applied in-kernel
    const float* uvqk_w   = (const float*)d_in[3];
    const float* uvqk_b   = (const float*)d_in[4];
    const float* gate_w   = (const float*)d_in[5];
    const float* out_w    = (const float*)d_in[6];
    const float* out_b    = (const float*)d_in[7];
    const float* in_nw    = (const float*)d_in[8];
    const float* last_nw  = (const float*)d_in[9];
    const int*   pos_ids  = (const int*)d_in[10];
    float* out = (float*)d_out;

    void *ph, *pu, *pattn, *pcs, *psn;
    void *pwqh, *pwql, *pwoh, *pwol, *pahi, *palo, *pghi, *pglo;
    void *pqh, *pql, *pkh, *pkl, *pvh, *pvl;
    cudaGetSymbolAddress(&ph, g_h);
    cudaGetSymbolAddress(&pu, g_u);
    cudaGetSymbolAddress(&pattn, g_attn);
    cudaGetSymbolAddress(&pcs, g_cs);
    cudaGetSymbolAddress(&psn, g_sn);
    cudaGetSymbolAddress(&pwqh, g_wqk_hi);
    cudaGetSymbolAddress(&pwql, g_wqk_lo);
    cudaGetSymbolAddress(&pwoh, g_wo_hi);
    cudaGetSymbolAddress(&pwol, g_wo_lo);
    cudaGetSymbolAddress(&pahi, g_ahi);
    cudaGetSymbolAddress(&palo, g_alo);
    cudaGetSymbolAddress(&pghi, g_ghi);
    cudaGetSymbolAddress(&pglo, g_glo);
    cudaGetSymbolAddress(&pqh, g_qhi);
    cudaGetSymbolAddress(&pql, g_qlo);
    cudaGetSymbolAddress(&pkh, g_khi);
    cudaGetSymbolAddress(&pkl, g_klo);
    cudaGetSymbolAddress(&pvh, g_vhi);
    cudaGetSymbolAddress(&pvl, g_vlo);
    float* h    = (float*)ph;
    float* u    = (float*)pu;
    float* attn = (float*)pattn;
    float* cs   = (float*)pcs;
    float* sn   = (float*)psn;
    __nv_bfloat16* wqh = (__nv_bfloat16*)pwqh;
    __nv_bfloat16* wql = (__nv_bfloat16*)pwql;
    __nv_bfloat16* woh = (__nv_bfloat16*)pwoh;
    __nv_bfloat16* wol = (__nv_bfloat16*)pwol;
    __nv_bfloat16* ahi = (__nv_bfloat16*)pahi;
    __nv_bfloat16* alo = (__nv_bfloat16*)palo;
    __nv_bfloat16* ghi = (__nv_bfloat16*)pghi;
    __nv_bfloat16* glo = (__nv_bfloat16*)pglo;
    __nv_bfloat16* qhi = (__nv_bfloat16*)pqh;
    __nv_bfloat16* qlo = (__nv_bfloat16*)pql;
    __nv_bfloat16* khi = (__nv_bfloat16*)pkh;
    __nv_bfloat16* klo = (__nv_bfloat16*)pkl;
    __nv_bfloat16* vhi = (__nv_bfloat16*)pvh;
    __nv_bfloat16* vlo = (__nv_bfloat16*)pvl;

    cudaFuncSetAttribute(attn_mma_k, cudaFuncAttributeMaxDynamicSharedMemorySize, ATTN_SMEM);
    cudaFuncSetAttribute(mmagemm_k<0>, cudaFuncAttributeMaxDynamicSharedMemorySize, GSMEM);
    cudaFuncSetAttribute(mmagemm_k<1>, cudaFuncAttributeMaxDynamicSharedMemorySize, GSMEM);
    cudaFuncSetAttribute(mmagemm_k<2>, cudaFuncAttributeMaxDynamicSharedMemorySize, GSMEM);

    // one-time: weight convert + rope table
    wconv_k<<<dim3(FOURD / 32, DD / 32, LL), dim3(32, 8)>>>(uvqk_w, wqh, wql, DD, FOURD);
    wconv_k<<<dim3(DD / 32, DD / 32, LL), dim3(32, 8)>>>(out_w, woh, wol, DD, DD);
    costab_k<<<(MROWS * 32) / 256, 256>>>(td, pos_ids, cs, sn);

    // h = rms_norm(x, in_norm_w), plus bf16 split into ahi/alo
    rmsnorm_k<true><<<MROWS, 256>>>(x, in_nw, h, ahi, alo);

    for (int l = 0; l < LL; l++) {
        const __nv_bfloat16* wqhl = wqh + (size_t)l * FOURD * DD;
        const __nv_bfloat16* wqll = wql + (size_t)l * FOURD * DD;
        const __nv_bfloat16* wohl = woh + (size_t)l * DD * DD;
        const __nv_bfloat16* woll = wol + (size_t)l * DD * DD;
        const float* bl  = uvqk_b + (size_t)l * FOURD;
        const float* gwl = gate_w + (size_t)l * DD;
        const float* obl = out_b + (size_t)l * DD;

        // uvqk GEMM with fused silu/rope/split epilogue
        mmagemm_k<2><<<dim3(FOURD / 256, MROWS / 128), 256, GSMEM>>>(
            FOURD, DD, ahi, alo, wqhl, wqll, bl, nullptr, nullptr, nullptr, nullptr,
            u, qhi, qlo, khi, klo, vhi, vlo, cs, sn);
        // attention (tensor cores)
        attn_mma_k<<<dim3(SS / 256, BB * HH), 256, ATTN_SMEM>>>(
            qhi, qlo, khi, klo, vhi, vlo, attn);
        // gated = rms_norm(attn, gate_w) * u -> split
        rmsgate_k<<<MROWS, 256>>>(attn, gwl, u, ghi, glo);
        // h = h + g @ out_w + out_b; split h for next layer's GEMM
        if (l + 1 < LL) {
            mmagemm_k<1><<<dim3(DD / 256, MROWS / 128), 256, GSMEM>>>(
                DD, DD, ghi, glo, wohl, woll, obl, h, h, ahi, alo,
                nullptr, nullptr, nullptr, nullptr, nullptr, nullptr, nullptr,
                nullptr, nullptr);
        } else {
            mmagemm_k<0><<<dim3(DD / 256, MROWS / 128), 256, GSMEM>>>(
                DD, DD, ghi, glo, wohl, woll, obl, h, h, nullptr, nullptr,
                nullptr, nullptr, nullptr, nullptr, nullptr, nullptr, nullptr,
                nullptr, nullptr);
        }
    }

    rmsnorm_k<false><<<MROWS, 256>>>(h, last_nw, out, nullptr, nullptr);
}

// round 11
// speedup vs baseline: 1.1099x; 1.1099x over previous
#include <cuda_runtime.h>
#include <cuda_bf16.h>
#include <math.h>
#include <stdint.h>

// Problem constants
#define BB 2
#define SS 2048
#define DD 1024
#define HH 16
#define HD 64
#define LL 4
#define MROWS (BB*SS)          // 4096
#define FOURD (4*DD)           // 4096

// ---------------------------------------------------------------------------
// Scratch (device globals; no allocation allowed)
// ---------------------------------------------------------------------------
__device__ float g_h[MROWS * DD];        // hidden state
__device__ float g_u[MROWS * DD];        // silu(u)
__device__ float g_attn[MROWS * DD];     // attention output
__device__ float g_cs[MROWS * 32];       // rope cos table (per token x 32 freqs)
__device__ float g_sn[MROWS * 32];       // rope sin table

__device__ __nv_bfloat16 g_wqk_hi[LL * FOURD * DD];  // uvqk_w^T split, [L][N=4D][K=D]
__device__ __nv_bfloat16 g_wqk_lo[LL * FOURD * DD];
__device__ __nv_bfloat16 g_wo_hi[LL * DD * DD];      // out_w^T split, [L][N=D][K=D]
__device__ __nv_bfloat16 g_wo_lo[LL * DD * DD];
__device__ __nv_bfloat16 g_ahi[MROWS * DD];          // h split (GEMM A input)
__device__ __nv_bfloat16 g_alo[MROWS * DD];
__device__ __nv_bfloat16 g_ghi[MROWS * DD];          // gated split (GEMM A input)
__device__ __nv_bfloat16 g_glo[MROWS * DD];
// q/k/v splits in [b,h,s,d] layout
__device__ __nv_bfloat16 g_qhi[MROWS * DD];
__device__ __nv_bfloat16 g_qlo[MROWS * DD];
__device__ __nv_bfloat16 g_khi[MROWS * DD];
__device__ __nv_bfloat16 g_klo[MROWS * DD];
__device__ __nv_bfloat16 g_vhi[MROWS * DD];
__device__ __nv_bfloat16 g_vlo[MROWS * DD];

// ---------------------------------------------------------------------------
// PTX helpers (legacy tensor-core path: valid under compute_103 PTX)
// ---------------------------------------------------------------------------
__device__ __forceinline__ uint32_t smem_u32(const void* p) {
    uint32_t a;
    asm("{ .reg .u64 t; cvta.to.shared.u64 t, %1; cvt.u32.u64 %0, t; }" : "=r"(a) : "l"(p));
    return a;
}
__device__ __forceinline__ void cp_async16(uint32_t dst, const void* src) {
    asm volatile("cp.async.cg.shared.global [%0], [%1], 16;" :: "r"(dst), "l"(src) : "memory");
}
#define CP_COMMIT()  asm volatile("cp.async.commit_group;" ::: "memory")
#define CP_WAIT0()   asm volatile("cp.async.wait_group 0;" ::: "memory")
#define CP_WAIT1()   asm volatile("cp.async.wait_group 1;" ::: "memory")
#define CP_WAIT2()   asm volatile("cp.async.wait_group 2;" ::: "memory")

__device__ __forceinline__ void ldsm4(uint32_t* r, uint32_t addr) {
    asm volatile("ldmatrix.sync.aligned.m8n8.x4.shared.b16 {%0,%1,%2,%3}, [%4];"
                 : "=r"(r[0]), "=r"(r[1]), "=r"(r[2]), "=r"(r[3]) : "r"(addr));
}
__device__ __forceinline__ void ldsm4t(uint32_t* r, uint32_t addr) {
    asm volatile("ldmatrix.sync.aligned.m8n8.x4.trans.shared.b16 {%0,%1,%2,%3}, [%4];"
                 : "=r"(r[0]), "=r"(r[1]), "=r"(r[2]), "=r"(r[3]) : "r"(addr));
}
__device__ __forceinline__ void mma_bf16(float* c, const uint32_t* a, const uint32_t* b) {
    asm volatile("mma.sync.aligned.m16n8k16.row.col.f32.bf16.bf16.f32 "
                 "{%0,%1,%2,%3}, {%4,%5,%6,%7}, {%8,%9}, {%0,%1,%2,%3};"
                 : "+f"(c[0]), "+f"(c[1]), "+f"(c[2]), "+f"(c[3])
                 : "r"(a[0]), "r"(a[1]), "r"(a[2]), "r"(a[3]), "r"(b[0]), "r"(b[1]));
}
// pack two fp32 into bf16x2 reg: lo goes to bits[15:0]
__device__ __forceinline__ uint32_t packbf(float lo, float hi) {
    uint32_t r;
    asm("cvt.rn.bf16x2.f32 %0, %1, %2;" : "=r"(r) : "f"(hi), "f"(lo));
    return r;
}
// split two fp32 into bf16 hi/lo pairs and store as bf16x2
__device__ __forceinline__ void split_store2(__nv_bfloat16* hi, __nv_bfloat16* lo,
                                             size_t off, float x, float y) {
    __nv_bfloat162 h, l;
    h.x = __float2bfloat16(x);
    h.y = __float2bfloat16(y);
    l.x = __float2bfloat16(x - __bfloat162float(h.x));
    l.y = __float2bfloat16(y - __bfloat162float(h.y));
    *reinterpret_cast<__nv_bfloat162*>(hi + off) = h;
    *reinterpret_cast<__nv_bfloat162*>(lo + off) = l;
}

// ---------------------------------------------------------------------------
// Weight convert+transpose+split: W[K,N] fp32 -> Thi/Tlo [N,K] bf16 (layer z)
// ---------------------------------------------------------------------------
__global__ void wconv_k(const float* __restrict__ W, __nv_bfloat16* __restrict__ Thi,
                        __nv_bfloat16* __restrict__ Tlo, int K, int N) {
    __shared__ float t[32][33];
    int l = blockIdx.z;
    const float* Wl = W + (size_t)l * K * N;
    __nv_bfloat16* Hl = Thi + (size_t)l * K * N;
    __nv_bfloat16* Ll = Tlo + (size_t)l * K * N;
    int n0 = blockIdx.x * 32, k0 = blockIdx.y * 32;
    int tx = threadIdx.x, ty = threadIdx.y;
    #pragma unroll
    for (int i = 0; i < 32; i += 8)
        t[ty + i][tx] = Wl[(size_t)(k0 + ty + i) * N + n0 + tx];
    __syncthreads();
    #pragma unroll
    for (int i = 0; i < 32; i += 8) {
        float v = t[tx][ty + i];
        __nv_bfloat16 hi = __float2bfloat16(v);
        __nv_bfloat16 lo = __float2bfloat16(v - __bfloat162float(hi));
        size_t o = (size_t)(n0 + ty + i) * K + k0 + tx;
        Hl[o] = hi;
        Ll[o] = lo;
    }
}

// ---------------------------------------------------------------------------
// RoPE cos/sin table: per token, 32 freqs (layer-invariant, computed once)
// ---------------------------------------------------------------------------
__global__ void costab_k(const float* __restrict__ td, const int* __restrict__ pos,
                         float* __restrict__ cs, float* __restrict__ sn) {
    int idx = blockIdx.x * blockDim.x + threadIdx.x;   // MROWS*32
    int t = idx >> 5, i = idx & 31;
    float p = (float)pos[t] + 0.1f * logf(td[t] + 1.0f);
    float invf = expf(-logf(10000.0f) * (float)i / 32.0f);
    float f = p * invf;
    cs[idx] = cosf(f);
    sn[idx] = sinf(f);
}

// ---------------------------------------------------------------------------
// mma.sync bf16x3 GEMM: C = Ahi*Bhi + Ahi*Blo + Alo*Bhi (+bias, epilogues)
// CTA tile 128x256, BK=32, 8 warps @ 64x64 (2M x 4N), double-buffer cp.async.
// EPI 0: C = acc+bias+res               (out-proj, last layer)
// EPI 1: EPI0 + bf16 hi/lo split of C   (out-proj, feeds next uvqk GEMM)
// EPI 2: fused uvqk epilogue: silu(u)->u buf; v split; q,k rope+split [b,h,s,d]
// ---------------------------------------------------------------------------
#define ROWB 80                  // bytes per smem row (64B data + 16B pad)
#define A_B (128 * ROWB)         // 10240 B per A array (128 rows)
#define B_B (256 * ROWB)         // 20480 B per B array (256 rows)
#define STG_B (2 * A_B + 2 * B_B)  // 61440 B per stage
#define GSMEM (2 * STG_B)        // 122880 B

template<int EPI>
__global__ __launch_bounds__(256, 1)
void mmagemm_k(int N, int K,
               const __nv_bfloat16* __restrict__ Ahi, const __nv_bfloat16* __restrict__ Alo,
               const __nv_bfloat16* __restrict__ Bhi, const __nv_bfloat16* __restrict__ Blo,
               const float* __restrict__ bias, const float* __restrict__ res,
               float* __restrict__ C,
               __nv_bfloat16* __restrict__ Chi, __nv_bfloat16* __restrict__ Clo,
               float* __restrict__ u,
               __nv_bfloat16* __restrict__ qhi, __nv_bfloat16* __restrict__ qlo,
               __nv_bfloat16* __restrict__ khi, __nv_bfloat16* __restrict__ klo,
               __nv_bfloat16* __restrict__ vhi, __nv_bfloat16* __restrict__ vlo,
               const float* __restrict__ cstab, const float* __restrict__ sntab) {
    extern __shared__ char dynsm[];
    const uint32_t sb = smem_u32(dynsm);
    const int tid = threadIdx.x;
    const int lane = tid & 31, wid = tid >> 5;
    const int warpM = (wid & 1) * 64;    // 0 or 64
    const int warpN = (wid >> 1) * 64;   // 0..192
    const int m0 = blockIdx.y * 128;
    const int n0 = blockIdx.x * 256;
    const int nk = K / 32;

    const __nv_bfloat16* Asrc[2] = { Ahi + (size_t)m0 * K, Alo + (size_t)m0 * K };
    const __nv_bfloat16* Bsrc[2] = { Bhi + (size_t)n0 * K, Blo + (size_t)n0 * K };

    auto load_stage = [&](int stage, int kc) {
        const int k0 = kc * 32;
        const uint32_t dbase = sb + stage * STG_B;
        #pragma unroll
        for (int j = 0; j < 12; j++) {
            int idx = tid + 256 * j;           // 0..3071
            int rg = idx >> 2;                 // 0..767
            int ch = idx & 3;
            uint32_t dst;
            const __nv_bfloat16* src;
            if (rg < 256) {
                int arr = rg >> 7, row = rg & 127;
                src = Asrc[arr] + (size_t)row * K + k0 + ch * 8;
                dst = dbase + arr * A_B + row * ROWB + ch * 16;
            } else {
                int rgb = rg - 256;
                int arr = rgb >> 8, row = rgb & 255;
                src = Bsrc[arr] + (size_t)row * K + k0 + ch * 8;
                dst = dbase + 2 * A_B + arr * B_B + row * ROWB + ch * 16;
            }
            cp_async16(dst, src);
        }
        CP_COMMIT();
    };

    const uint32_t aoff = (uint32_t)(warpM + (lane & 15)) * ROWB + (lane >> 4) * 16;
    const uint32_t boff = (uint32_t)(warpN + (lane >> 4) * 8 + (lane & 7)) * ROWB
                          + ((lane >> 3) & 1) * 16;

    float acc[4][8][4] = {};

    load_stage(0, 0);

    for (int kc = 0; kc < nk; kc++) {
        if (kc + 1 < nk) {
            load_stage((kc + 1) & 1, kc + 1);
            CP_WAIT1();
        } else {
            CP_WAIT0();
        }
        __syncthreads();

        const uint32_t stb = sb + (kc & 1) * STG_B;
        #pragma unroll
        for (int ks = 0; ks < 2; ks++) {
            const uint32_t ko = ks * 32;
            uint32_t ah[4][4], al[4][4];
            #pragma unroll
            for (int mt = 0; mt < 4; mt++) {
                uint32_t a = stb + aoff + mt * (16 * ROWB) + ko;
                ldsm4(ah[mt], a);
                ldsm4(al[mt], a + A_B);
            }
            #pragma unroll
            for (int p = 0; p < 4; p++) {
                uint32_t bh[4], bl[4];
                uint32_t b = stb + 2 * A_B + boff + p * (16 * ROWB) + ko;
                ldsm4(bh, b);
                ldsm4(bl, b + B_B);
                #pragma unroll
                for (int mt = 0; mt < 4; mt++) {
                    #pragma unroll
                    for (int half = 0; half < 2; half++) {
                        float* c = acc[mt][2 * p + half];
                        mma_bf16(c, ah[mt], &bh[half * 2]);
                        mma_bf16(c, ah[mt], &bl[half * 2]);
                        mma_bf16(c, al[mt], &bh[half * 2]);
                    }
                }
            }
        }
        __syncthreads();
    }

    const int frow = lane >> 2;
    const int fcol = (lane & 3) * 2;

    if (EPI == 2) {
        // ---- fused uvqk epilogue ----
        const int gcol0 = n0 + warpN;              // head-aligned (64)
        const int region = gcol0 >> 10;            // 0=u 1=v 2=q 3=k
        const int hh = (gcol0 & 1023) >> 6;        // head index
        #pragma unroll
        for (int mt = 0; mt < 4; mt++) {
            const int mr0 = m0 + warpM + mt * 16 + frow;
            const int mr1 = mr0 + 8;
            const int b0 = mr0 >> 11, s0 = mr0 & (SS - 1);
            const int b1 = mr1 >> 11, s1 = mr1 & (SS - 1);
            const size_t ob0 = ((size_t)(b0 * HH + hh) * SS + s0) * HD;
            const size_t ob1 = ((size_t)(b1 * HH + hh) * SS + s1) * HD;
            if (region == 0) {
                #pragma unroll
                for (int nt = 0; nt < 8; nt++) {
                    const int n = gcol0 + nt * 8 + fcol;
                    const float* a = acc[mt][nt];
                    float2 bv = *reinterpret_cast<const float2*>(bias + n);
                    float x0 = a[0] + bv.x, y0 = a[1] + bv.y;
                    float x1 = a[2] + bv.x, y1 = a[3] + bv.y;
                    x0 = x0 / (1.0f + __expf(-x0));
                    y0 = y0 / (1.0f + __expf(-y0));
                    x1 = x1 / (1.0f + __expf(-x1));
                    y1 = y1 / (1.0f + __expf(-y1));
                    *reinterpret_cast<float2*>(u + (size_t)mr0 * DD + n) = make_float2(x0, y0);
                    *reinterpret_cast<float2*>(u + (size_t)mr1 * DD + n) = make_float2(x1, y1);
                }
            } else if (region == 1) {
                #pragma unroll
                for (int nt = 0; nt < 8; nt++) {
                    const int d0 = nt * 8 + fcol;
                    const int n = gcol0 + d0;
                    const float* a = acc[mt][nt];
                    float2 bv = *reinterpret_cast<const float2*>(bias + n);
                    split_store2(vhi, vlo, ob0 + d0, a[0] + bv.x, a[1] + bv.y);
                    split_store2(vhi, vlo, ob1 + d0, a[2] + bv.x, a[3] + bv.y);
                }
            } else {
                __nv_bfloat16* dhi = (region == 2) ? qhi : khi;
                __nv_bfloat16* dlo = (region == 2) ? qlo : klo;
                #pragma unroll
                for (int nt = 0; nt < 4; nt++) {
                    const int d0 = nt * 8 + fcol;          // 0..30
                    const int n = gcol0 + d0;
                    const float* a1 = acc[mt][nt];         // cols d0, d0+1
                    const float* a2 = acc[mt][nt + 4];     // cols d0+32, d0+33
                    float2 bv1 = *reinterpret_cast<const float2*>(bias + n);
                    float2 bv2 = *reinterpret_cast<const float2*>(bias + n + 32);
                    // row mr0
                    {
                        float2 c2 = *reinterpret_cast<const float2*>(cstab + (size_t)mr0 * 32 + d0);
                        float2 s2 = *reinterpret_cast<const float2*>(sntab + (size_t)mr0 * 32 + d0);
                        float q1a = a1[0] + bv1.x, q1b = a1[1] + bv1.y;
                        float q2a = a2[0] + bv2.x, q2b = a2[1] + bv2.y;
                        split_store2(dhi, dlo, ob0 + d0,
                                     q1a * c2.x - q2a * s2.x, q1b * c2.y - q2b * s2.y);
                        split_store2(dhi, dlo, ob0 + d0 + 32,
                                     q2a * c2.x + q1a * s2.x, q2b * c2.y + q1b * s2.y);
                    }
                    // row mr1
                    {
                        float2 c2 = *reinterpret_cast<const float2*>(cstab + (size_t)mr1 * 32 + d0);
                        float2 s2 = *reinterpret_cast<const float2*>(sntab + (size_t)mr1 * 32 + d0);
                        float q1a = a1[2] + bv1.x, q1b = a1[3] + bv1.y;
                        float q2a = a2[2] + bv2.x, q2b = a2[3] + bv2.y;
                        split_store2(dhi, dlo, ob1 + d0,
                                     q1a * c2.x - q2a * s2.x, q1b * c2.y - q2b * s2.y);
                        split_store2(dhi, dlo, ob1 + d0 + 32,
                                     q2a * c2.x + q1a * s2.x, q2b * c2.y + q1b * s2.y);
                    }
                }
            }
        }
    } else {
        // ---- out-proj epilogue: C = acc + bias + res (+ optional split) ----
        #pragma unroll
        for (int mt = 0; mt < 4; mt++) {
            const int m = m0 + warpM + mt * 16 + frow;
            #pragma unroll
            for (int nt = 0; nt < 8; nt++) {
                const int n = n0 + warpN + nt * 8 + fcol;
                const float* a = acc[mt][nt];
                float2 bv = *reinterpret_cast<const float2*>(bias + n);
                float2 r0 = *reinterpret_cast<const float2*>(res + (size_t)m * N + n);
                float2 r1 = *reinterpret_cast<const float2*>(res + (size_t)(m + 8) * N + n);
                float2 o0 = { a[0] + bv.x + r0.x, a[1] + bv.y + r0.y };
                float2 o1 = { a[2] + bv.x + r1.x, a[3] + bv.y + r1.y };
                *reinterpret_cast<float2*>(C + (size_t)m * N + n) = o0;
                *reinterpret_cast<float2*>(C + (size_t)(m + 8) * N + n) = o1;
                if (EPI == 1) {
                    split_store2(Chi, Clo, (size_t)m * N + n, o0.x, o0.y);
                    split_store2(Chi, Clo, (size_t)(m + 8) * N + n, o1.x, o1.y);
                }
            }
        }
    }
}

// ---------------------------------------------------------------------------
// block reduce (256 threads)
// ---------------------------------------------------------------------------
__device__ __forceinline__ float blockReduceSum(float v) {
    __shared__ float red[8];
    int lane = threadIdx.x & 31, wid = threadIdx.x >> 5;
    #pragma unroll
    for (int o = 16; o; o >>= 1) v += __shfl_down_sync(0xFFFFFFFFu, v, o);
    if (lane == 0) red[wid] = v;
    __syncthreads();
    float r = 0.f;
    if (threadIdx.x < 8) r = red[threadIdx.x];
    if (wid == 0) {
        #pragma unroll
        for (int o = 4; o; o >>= 1) r += __shfl_down_sync(0xFFFFFFFFu, r, o);
        if (lane == 0) red[0] = r;
    }
    __syncthreads();
    return red[0];
}

// RMS norm, vectorized: one row per 256-thread block (4 elems/thread).
template<bool SPLIT>
__global__ void rmsnorm_k(const float* __restrict__ in, const float* __restrict__ w,
                          float* __restrict__ out,
                          __nv_bfloat16* __restrict__ ohi, __nv_bfloat16* __restrict__ olo) {
    const int row = blockIdx.x, t = threadIdx.x;
    const size_t off = (size_t)row * DD + t * 4;
    float4 v = *reinterpret_cast<const float4*>(in + off);
    float ss = v.x * v.x + v.y * v.y + v.z * v.z + v.w * v.w;
    float tot = blockReduceSum(ss);
    float inv = rsqrtf(tot / (float)DD + 1e-6f);
    float4 wv = *reinterpret_cast<const float4*>(w + t * 4);
    float4 y = { v.x * wv.x * inv, v.y * wv.y * inv, v.z * wv.z * inv, v.w * wv.w * inv };
    *reinterpret_cast<float4*>(out + off) = y;
    if (SPLIT) {
        split_store2(ohi, olo, off, y.x, y.y);
        split_store2(ohi, olo, off + 2, y.z, y.w);
    }
}

// gated = rms_norm(attn, gate_w) * u  -> bf16 hi/lo split only (vectorized)
__global__ void rmsgate_k(const float* __restrict__ attn, const float* __restrict__ gw,
                          const float* __restrict__ u,
                          __nv_bfloat16* __restrict__ ghi, __nv_bfloat16* __restrict__ glo) {
    const int row = blockIdx.x, t = threadIdx.x;
    const size_t off = (size_t)row * DD + t * 4;
    float4 v = *reinterpret_cast<const float4*>(attn + off);
    float ss = v.x * v.x + v.y * v.y + v.z * v.z + v.w * v.w;
    float tot = blockReduceSum(ss);
    float inv = rsqrtf(tot / (float)DD + 1e-6f);
    float4 wv = *reinterpret_cast<const float4*>(gw + t * 4);
    float4 uv = *reinterpret_cast<const float4*>(u + off);
    float y0 = v.x * wv.x * inv * uv.x;
    float y1 = v.y * wv.y * inv * uv.y;
    float y2 = v.z * wv.z * inv * uv.z;
    float y3 = v.w * wv.w * inv * uv.w;
    split_store2(ghi, glo, off, y0, y1);
    split_store2(ghi, glo, off + 2, y2, y3);
}

// ---------------------------------------------------------------------------
// Tensor-core causal SiLU attention, bf16x3.
// grid=(S/128, B*H), 256 threads (8 warps x 16 q-rows).
// Q fragments hoisted to registers (loaded once). qt reversed for balance.
// K/V tiles 64 keys, 3-stage cp.async pipeline. W split in registers for PV.
// ---------------------------------------------------------------------------
#define AROWB 144                 // 72 elems * 2B, 16B-aligned
#define QA (128 * AROWB)          // 18432 B per Q array
#define KVA (64 * AROWB)          // 9216 B per KV array
#define KVSTG (4 * KVA)           // 36864 B per stage (khi,klo,vhi,vlo)
#define ATTN_SMEM (2 * QA + 3 * KVSTG)   // 147456 B

__global__ __launch_bounds__(256, 1)
void attn_mma_k(const __nv_bfloat16* __restrict__ qhi, const __nv_bfloat16* __restrict__ qlo,
                const __nv_bfloat16* __restrict__ khi, const __nv_bfloat16* __restrict__ klo,
                const __nv_bfloat16* __restrict__ vhi, const __nv_bfloat16* __restrict__ vlo,
                float* __restrict__ out) {
    extern __shared__ char dynsm[];
    const uint32_t sb = smem_u32(dynsm);
    const int tid = threadIdx.x;
    const int lane = tid & 31, wid = tid >> 5;
    const int qt = gridDim.x - 1 - blockIdx.x;    // heavy tiles first
    const int bh = blockIdx.y;
    const int b = bh >> 4, h = bh & 15;
    const int q0 = qt * 128;
    const int nkt = 2 * qt + 2;

    const size_t hb = (size_t)bh * SS;

    // ---- load Q (hi/lo) ----
    {
        const __nv_bfloat16* qsrc[2] = { qhi + (hb + q0) * HD, qlo + (hb + q0) * HD };
        #pragma unroll
        for (int j = 0; j < 8; j++) {
            int idx = tid + 256 * j;
            int arr = idx >> 10, rem = idx & 1023;
            int row = rem >> 3, seg = rem & 7;
            cp_async16(sb + arr * QA + row * AROWB + seg * 16,
                       qsrc[arr] + (size_t)row * HD + seg * 8);
        }
        CP_COMMIT();
    }

    const __nv_bfloat16* kvsrc[4] = { khi + hb * HD, klo + hb * HD,
                                      vhi + hb * HD, vlo + hb * HD };
    auto load_kv = [&](int stage, int kt) {
        const int k0 = kt * 64;
        const uint32_t dbase = sb + 2 * QA + stage * KVSTG;
        #pragma unroll
        for (int j = 0; j < 8; j++) {
            int idx = tid + 256 * j;
            int arr = idx >> 9, rem = idx & 511;
            int row = rem >> 3, seg = rem & 7;
            cp_async16(dbase + arr * KVA + row * AROWB + seg * 16,
                       kvsrc[arr] + (size_t)(k0 + row) * HD + seg * 8);
        }
        CP_COMMIT();
    };

    load_kv(0, 0);
    load_kv(1, 1);

    const uint32_t aoff = (uint32_t)(wid * 16 + (lane & 15)) * AROWB + (lane >> 4) * 16;
    const uint32_t boff = (uint32_t)((lane >> 4) * 8 + (lane & 7)) * AROWB + ((lane >> 3) & 1) * 16;
    const uint32_t voff = (uint32_t)(((lane >> 3) & 1) * 8 + (lane & 7)) * AROWB + (lane >> 4) * 16;

    // ---- hoist Q fragments into registers (reused across all kt tiles) ----
    uint32_t qH[4][4], qL[4][4];
    {
        CP_WAIT2();          // Q group complete (kv0, kv1 may be pending)
        __syncthreads();
        #pragma unroll
        for (int ks = 0; ks < 4; ks++) {
            ldsm4(qH[ks], sb + aoff + ks * 32);
            ldsm4(qL[ks], sb + QA + aoff + ks * 32);
        }
    }

    const int rbase = q0 + wid * 16 + (lane >> 2);
    float o[8][4] = {};

    for (int kt = 0; kt < nkt; kt++) {
        if (kt + 1 < nkt) { CP_WAIT1(); } else { CP_WAIT0(); }
        __syncthreads();

        const int k0 = kt * 64;
        const uint32_t kb = sb + 2 * QA + (kt % 3) * KVSTG;

        if (k0 <= q0 + wid * 16 + 15) {
            // ---- S = Q K^T (bf16x3, Q from registers) ----
            float s[8][4] = {};
            #pragma unroll
            for (int ks = 0; ks < 4; ks++) {
                #pragma unroll
                for (int p = 0; p < 4; p++) {
                    uint32_t bH[4], bL[4];
                    uint32_t ba = kb + boff + p * (16 * AROWB) + ks * 32;
                    ldsm4(bH, ba);
                    ldsm4(bL, ba + KVA);
                    #pragma unroll
                    for (int half = 0; half < 2; half++) {
                        float* acc = s[2 * p + half];
                        mma_bf16(acc, qH[ks], &bH[half * 2]);
                        mma_bf16(acc, qH[ks], &bL[half * 2]);
                        mma_bf16(acc, qL[ks], &bH[half * 2]);
                    }
                }
            }
            // ---- silu + causal mask ----
            const bool needmask = (k0 + 63 > q0 + wid * 16);
            #pragma unroll
            for (int n = 0; n < 8; n++) {
                int col0 = k0 + 8 * n + (lane & 3) * 2;
                #pragma unroll
                for (int e = 0; e < 4; e++) {
                    int r = rbase + ((e >> 1) ? 8 : 0);
                    int c = col0 + (e & 1);
                    float v = s[n][e] * 0.125f;
                    v = v / (1.0f + __expf(-v));
                    if (needmask && c > r) v = 0.0f;
                    s[n][e] = v;
                }
            }
            // ---- O += W V (bf16x3, W split in registers) ----
            #pragma unroll
            for (int kk = 0; kk < 4; kk++) {
                const float* t0 = s[2 * kk];
                const float* t1 = s[2 * kk + 1];
                float h00 = __bfloat162float(__float2bfloat16(t0[0]));
                float h01 = __bfloat162float(__float2bfloat16(t0[1]));
                float h02 = __bfloat162float(__float2bfloat16(t0[2]));
                float h03 = __bfloat162float(__float2bfloat16(t0[3]));
                float h10 = __bfloat162float(__float2bfloat16(t1[0]));
                float h11 = __bfloat162float(__float2bfloat16(t1[1]));
                float h12 = __bfloat162float(__float2bfloat16(t1[2]));
                float h13 = __bfloat162float(__float2bfloat16(t1[3]));
                uint32_t wh[4], wl[4];
                wh[0] = packbf(h00, h01); wh[1] = packbf(h02, h03);
                wh[2] = packbf(h10, h11); wh[3] = packbf(h12, h13);
                wl[0] = packbf(t0[0] - h00, t0[1] - h01);
                wl[1] = packbf(t0[2] - h02, t0[3] - h03);
                wl[2] = packbf(t1[0] - h10, t1[1] - h11);
                wl[3] = packbf(t1[2] - h12, t1[3] - h13);
                #pragma unroll
                for (int dg = 0; dg < 4; dg++) {
                    uint32_t va = kb + 2 * KVA + kk * (16 * AROWB) + voff + dg * 32;
                    uint32_t vH[4], vL[4];
                    ldsm4t(vH, va);
                    ldsm4t(vL, va + KVA);
                    #pragma unroll
                    for (int half = 0; half < 2; half++) {
                        float* acc = o[2 * dg + half];
                        mma_bf16(acc, wh, &vH[half * 2]);
                        mma_bf16(acc, wh, &vL[half * 2]);
                        mma_bf16(acc, wl, &vH[half * 2]);
                    }
                }
            }
        }

        if (kt + 2 < nkt) load_kv((kt + 2) % 3, kt + 2);
    }

    const int row0 = q0 + wid * 16 + (lane >> 2);
    #pragma unroll
    for (int dt = 0; dt < 8; dt++) {
        int col = h * HD + dt * 8 + (lane & 3) * 2;
        *reinterpret_cast<float2*>(out + (size_t)(b * SS + row0) * DD + col) =
            make_float2(o[dt][0], o[dt][1]);
        *reinterpret_cast<float2*>(out + (size_t)(b * SS + row0 + 8) * DD + col) =
            make_float2(o[dt][2], o[dt][3]);
    }
}

// ---------------------------------------------------------------------------
// kernel_launch
// ---------------------------------------------------------------------------
extern "C" void kernel_launch(void* const* d_in, const int* in_sizes, int n_in,
                              void* d_out, int out_size) {
    const float* x        = (const float*)d_in[0];
    const float* td       = (const float*)d_in[1];
    // d_in[2] = attn_mask: structurally tril(ones) -> causal mask applied in-kernel
    const float* uvqk_w   = (const float*)d_in[3];
    const float* uvqk_b   = (const float*)d_in[4];
    const float* gate_w   = (const float*)d_in[5];
    const float* out_w    = (const float*)d_in[6];
    const float* out_b    = (const float*)d_in[7];
    const float* in_nw    = (const float*)d_in[8];
    const float* last_nw  = (const float*)d_in[9];
    const int*   pos_ids  = (const int*)d_in[10];
    float* out = (float*)d_out;

    void *ph, *pu, *pattn, *pcs, *psn;
    void *pwqh, *pwql, *pwoh, *pwol, *pahi, *palo, *pghi, *pglo;
    void *pqh, *pql, *pkh, *pkl, *pvh, *pvl;
    cudaGetSymbolAddress(&ph, g_h);
    cudaGetSymbolAddress(&pu, g_u);
    cudaGetSymbolAddress(&pattn, g_attn);
    cudaGetSymbolAddress(&pcs, g_cs);
    cudaGetSymbolAddress(&psn, g_sn);
    cudaGetSymbolAddress(&pwqh, g_wqk_hi);
    cudaGetSymbolAddress(&pwql, g_wqk_lo);
    cudaGetSymbolAddress(&pwoh, g_wo_hi);
    cudaGetSymbolAddress(&pwol, g_wo_lo);
    cudaGetSymbolAddress(&pahi, g_ahi);
    cudaGetSymbolAddress(&palo, g_alo);
    cudaGetSymbolAddress(&pghi, g_ghi);
    cudaGetSymbolAddress(&pglo, g_glo);
    cudaGetSymbolAddress(&pqh, g_qhi);
    cudaGetSymbolAddress(&pql, g_qlo);
    cudaGetSymbolAddress(&pkh, g_khi);
    cudaGetSymbolAddress(&pkl, g_klo);
    cudaGetSymbolAddress(&pvh, g_vhi);
    cudaGetSymbolAddress(&pvl, g_vlo);
    float* h    = (float*)ph;
    float* u    = (float*)pu;
    float* attn = (float*)pattn;
    float* cs   = (float*)pcs;
    float* sn   = (float*)psn;
    __nv_bfloat16* wqh = (__nv_bfloat16*)pwqh;
    __nv_bfloat16* wql = (__nv_bfloat16*)pwql;
    __nv_bfloat16* woh = (__nv_bfloat16*)pwoh;
    __nv_bfloat16* wol = (__nv_bfloat16*)pwol;
    __nv_bfloat16* ahi = (__nv_bfloat16*)pahi;
    __nv_bfloat16* alo = (__nv_bfloat16*)palo;
    __nv_bfloat16* ghi = (__nv_bfloat16*)pghi;
    __nv_bfloat16* glo = (__nv_bfloat16*)pglo;
    __nv_bfloat16* qhi = (__nv_bfloat16*)pqh;
    __nv_bfloat16* qlo = (__nv_bfloat16*)pql;
    __nv_bfloat16* khi = (__nv_bfloat16*)pkh;
    __nv_bfloat16* klo = (__nv_bfloat16*)pkl;
    __nv_bfloat16* vhi = (__nv_bfloat16*)pvh;
    __nv_bfloat16* vlo = (__nv_bfloat16*)pvl;

    cudaFuncSetAttribute(attn_mma_k, cudaFuncAttributeMaxDynamicSharedMemorySize, ATTN_SMEM);
    cudaFuncSetAttribute(mmagemm_k<0>, cudaFuncAttributeMaxDynamicSharedMemorySize, GSMEM);
    cudaFuncSetAttribute(mmagemm_k<1>, cudaFuncAttributeMaxDynamicSharedMemorySize, GSMEM);
    cudaFuncSetAttribute(mmagemm_k<2>, cudaFuncAttributeMaxDynamicSharedMemorySize, GSMEM);

    // one-time: weight convert + rope table
    wconv_k<<<dim3(FOURD / 32, DD / 32, LL), dim3(32, 8)>>>(uvqk_w, wqh, wql, DD, FOURD);
    wconv_k<<<dim3(DD / 32, DD / 32, LL), dim3(32, 8)>>>(out_w, woh, wol, DD, DD);
    costab_k<<<(MROWS * 32) / 256, 256>>>(td, pos_ids, cs, sn);

    // h = rms_norm(x, in_norm_w), plus bf16 split into ahi/alo
    rmsnorm_k<true><<<MROWS, 256>>>(x, in_nw, h, ahi, alo);

    for (int l = 0; l < LL; l++) {
        const __nv_bfloat16* wqhl = wqh + (size_t)l * FOURD * DD;
        const __nv_bfloat16* wqll = wql + (size_t)l * FOURD * DD;
        const __nv_bfloat16* wohl = woh + (size_t)l * DD * DD;
        const __nv_bfloat16* woll = wol + (size_t)l * DD * DD;
        const float* bl  = uvqk_b + (size_t)l * FOURD;
        const float* gwl = gate_w + (size_t)l * DD;
        const float* obl = out_b + (size_t)l * DD;

        // uvqk GEMM with fused silu/rope/split epilogue
        mmagemm_k<2><<<dim3(FOURD / 256, MROWS / 128), 256, GSMEM>>>(
            FOURD, DD, ahi, alo, wqhl, wqll, bl, nullptr, nullptr, nullptr, nullptr,
            u, qhi, qlo, khi, klo, vhi, vlo, cs, sn);
        // attention (tensor cores)
        attn_mma_k<<<dim3(SS / 128, BB * HH), 256, ATTN_SMEM>>>(
            qhi, qlo, khi, klo, vhi, vlo, attn);
        // gated = rms_norm(attn, gate_w) * u -> split
        rmsgate_k<<<MROWS, 256>>>(attn, gwl, u, ghi, glo);
        // h = h + g @ out_w + out_b; split h for next layer's GEMM
        if (l + 1 < LL) {
            mmagemm_k<1><<<dim3(DD / 256, MROWS / 128), 256, GSMEM>>>(
                DD, DD, ghi, glo, wohl, woll, obl, h, h, ahi, alo,
                nullptr, nullptr, nullptr, nullptr, nullptr, nullptr, nullptr,
                nullptr, nullptr);
        } else {
            mmagemm_k<0><<<dim3(DD / 256, MROWS / 128), 256, GSMEM>>>(
                DD, DD, ghi, glo, wohl, woll, obl, h, h, nullptr, nullptr,
                nullptr, nullptr, nullptr, nullptr, nullptr, nullptr, nullptr,
                nullptr, nullptr);
        }
    }

    rmsnorm_k<false><<<MROWS, 256>>>(h, last_nw, out, nullptr, nullptr);
}

// round 12
// speedup vs baseline: 1.3379x; 1.2054x over previous
#include <cuda_runtime.h>
#include <cuda_bf16.h>
#include <math.h>
#include <stdint.h>

// Problem constants
#define BB 2
#define SS 2048
#define DD 1024
#define HH 16
#define HD 64
#define LL 4
#define MROWS (BB*SS)          // 4096
#define FOURD (4*DD)           // 4096

// ---------------------------------------------------------------------------
// Scratch (device globals; no allocation allowed)
// ---------------------------------------------------------------------------
__device__ float g_h[MROWS * DD];        // hidden state
__device__ float g_u[MROWS * DD];        // silu(u)
__device__ float g_attn[MROWS * DD];     // attention output
__device__ float g_cs[MROWS * 32];       // rope cos table (per token x 32 freqs)
__device__ float g_sn[MROWS * 32];       // rope sin table

__device__ __nv_bfloat16 g_wqk_hi[LL * FOURD * DD];  // uvqk_w^T split, [L][N=4D][K=D]
__device__ __nv_bfloat16 g_wqk_lo[LL * FOURD * DD];
__device__ __nv_bfloat16 g_wo_hi[LL * DD * DD];      // out_w^T split, [L][N=D][K=D]
__device__ __nv_bfloat16 g_wo_lo[LL * DD * DD];
__device__ __nv_bfloat16 g_ahi[MROWS * DD];          // h split (GEMM A input)
__device__ __nv_bfloat16 g_alo[MROWS * DD];
__device__ __nv_bfloat16 g_ghi[MROWS * DD];          // gated split (GEMM A input)
__device__ __nv_bfloat16 g_glo[MROWS * DD];
// q/k/v splits in [b,h,s,d] layout
__device__ __nv_bfloat16 g_qhi[MROWS * DD];
__device__ __nv_bfloat16 g_qlo[MROWS * DD];
__device__ __nv_bfloat16 g_khi[MROWS * DD];
__device__ __nv_bfloat16 g_klo[MROWS * DD];
__device__ __nv_bfloat16 g_vhi[MROWS * DD];
__device__ __nv_bfloat16 g_vlo[MROWS * DD];

// ---------------------------------------------------------------------------
// PTX helpers (legacy tensor-core path: valid under compute_103 PTX)
// ---------------------------------------------------------------------------
__device__ __forceinline__ uint32_t smem_u32(const void* p) {
    uint32_t a;
    asm("{ .reg .u64 t; cvta.to.shared.u64 t, %1; cvt.u32.u64 %0, t; }" : "=r"(a) : "l"(p));
    return a;
}
__device__ __forceinline__ void cp_async16(uint32_t dst, const void* src) {
    asm volatile("cp.async.cg.shared.global [%0], [%1], 16;" :: "r"(dst), "l"(src) : "memory");
}
#define CP_COMMIT()  asm volatile("cp.async.commit_group;" ::: "memory")
#define CP_WAIT0()   asm volatile("cp.async.wait_group 0;" ::: "memory")
#define CP_WAIT1()   asm volatile("cp.async.wait_group 1;" ::: "memory")
#define CP_WAIT2()   asm volatile("cp.async.wait_group 2;" ::: "memory")

__device__ __forceinline__ void ldsm4(uint32_t* r, uint32_t addr) {
    asm volatile("ldmatrix.sync.aligned.m8n8.x4.shared.b16 {%0,%1,%2,%3}, [%4];"
                 : "=r"(r[0]), "=r"(r[1]), "=r"(r[2]), "=r"(r[3]) : "r"(addr));
}
__device__ __forceinline__ void ldsm4t(uint32_t* r, uint32_t addr) {
    asm volatile("ldmatrix.sync.aligned.m8n8.x4.trans.shared.b16 {%0,%1,%2,%3}, [%4];"
                 : "=r"(r[0]), "=r"(r[1]), "=r"(r[2]), "=r"(r[3]) : "r"(addr));
}
__device__ __forceinline__ void mma_bf16(float* c, const uint32_t* a, const uint32_t* b) {
    asm volatile("mma.sync.aligned.m16n8k16.row.col.f32.bf16.bf16.f32 "
                 "{%0,%1,%2,%3}, {%4,%5,%6,%7}, {%8,%9}, {%0,%1,%2,%3};"
                 : "+f"(c[0]), "+f"(c[1]), "+f"(c[2]), "+f"(c[3])
                 : "r"(a[0]), "r"(a[1]), "r"(a[2]), "r"(a[3]), "r"(b[0]), "r"(b[1]));
}
// pack two fp32 into bf16x2 reg: lo goes to bits[15:0]
__device__ __forceinline__ uint32_t packbf(float lo, float hi) {
    uint32_t r;
    asm("cvt.rn.bf16x2.f32 %0, %1, %2;" : "=r"(r) : "f"(hi), "f"(lo));
    return r;
}
// fast tanh
__device__ __forceinline__ float fast_tanh(float x) {
    float t;
    asm("tanh.approx.f32 %0, %1;" : "=f"(t) : "f"(x));
    return t;
}
// split two fp32 into bf16 hi/lo pairs and store as bf16x2
__device__ __forceinline__ void split_store2(__nv_bfloat16* hi, __nv_bfloat16* lo,
                                             size_t off, float x, float y) {
    __nv_bfloat162 h, l;
    h.x = __float2bfloat16(x);
    h.y = __float2bfloat16(y);
    l.x = __float2bfloat16(x - __bfloat162float(h.x));
    l.y = __float2bfloat16(y - __bfloat162float(h.y));
    *reinterpret_cast<__nv_bfloat162*>(hi + off) = h;
    *reinterpret_cast<__nv_bfloat162*>(lo + off) = l;
}

// ---------------------------------------------------------------------------
// Weight convert+transpose+split: W[K,N] fp32 -> Thi/Tlo [N,K] bf16 (layer z)
// ---------------------------------------------------------------------------
__global__ void wconv_k(const float* __restrict__ W, __nv_bfloat16* __restrict__ Thi,
                        __nv_bfloat16* __restrict__ Tlo, int K, int N) {
    __shared__ float t[32][33];
    int l = blockIdx.z;
    const float* Wl = W + (size_t)l * K * N;
    __nv_bfloat16* Hl = Thi + (size_t)l * K * N;
    __nv_bfloat16* Ll = Tlo + (size_t)l * K * N;
    int n0 = blockIdx.x * 32, k0 = blockIdx.y * 32;
    int tx = threadIdx.x, ty = threadIdx.y;
    #pragma unroll
    for (int i = 0; i < 32; i += 8)
        t[ty + i][tx] = Wl[(size_t)(k0 + ty + i) * N + n0 + tx];
    __syncthreads();
    #pragma unroll
    for (int i = 0; i < 32; i += 8) {
        float v = t[tx][ty + i];
        __nv_bfloat16 hi = __float2bfloat16(v);
        __nv_bfloat16 lo = __float2bfloat16(v - __bfloat162float(hi));
        size_t o = (size_t)(n0 + ty + i) * K + k0 + tx;
        Hl[o] = hi;
        Ll[o] = lo;
    }
}

// ---------------------------------------------------------------------------
// RoPE cos/sin table: per token, 32 freqs (layer-invariant, computed once)
// ---------------------------------------------------------------------------
__global__ void costab_k(const float* __restrict__ td, const int* __restrict__ pos,
                         float* __restrict__ cs, float* __restrict__ sn) {
    int idx = blockIdx.x * blockDim.x + threadIdx.x;   // MROWS*32
    int t = idx >> 5, i = idx & 31;
    float p = (float)pos[t] + 0.1f * logf(td[t] + 1.0f);
    float invf = expf(-logf(10000.0f) * (float)i / 32.0f);
    float f = p * invf;
    cs[idx] = cosf(f);
    sn[idx] = sinf(f);
}

// ---------------------------------------------------------------------------
// mma.sync bf16x3 GEMM: C = Ahi*Bhi + Ahi*Blo + Alo*Bhi (+bias, epilogues)
// CTA tile 128x256, BK=32, 8 warps @ 64x64 (2M x 4N), double-buffer cp.async.
// EPI 0: C = acc+bias+res               (out-proj, last layer)
// EPI 1: EPI0 + bf16 hi/lo split of C   (out-proj, feeds next uvqk GEMM)
// EPI 2: fused uvqk epilogue: silu(u)->u buf; v split; q,k rope+split [b,h,s,d]
// ---------------------------------------------------------------------------
#define ROWB 80                  // bytes per smem row (64B data + 16B pad)
#define A_B (128 * ROWB)         // 10240 B per A array (128 rows)
#define B_B (256 * ROWB)         // 20480 B per B array (256 rows)
#define STG_B (2 * A_B + 2 * B_B)  // 61440 B per stage
#define GSMEM (2 * STG_B)        // 122880 B

template<int EPI>
__global__ __launch_bounds__(256, 1)
void mmagemm_k(int N, int K,
               const __nv_bfloat16* __restrict__ Ahi, const __nv_bfloat16* __restrict__ Alo,
               const __nv_bfloat16* __restrict__ Bhi, const __nv_bfloat16* __restrict__ Blo,
               const float* __restrict__ bias, const float* __restrict__ res,
               float* __restrict__ C,
               __nv_bfloat16* __restrict__ Chi, __nv_bfloat16* __restrict__ Clo,
               float* __restrict__ u,
               __nv_bfloat16* __restrict__ qhi, __nv_bfloat16* __restrict__ qlo,
               __nv_bfloat16* __restrict__ khi, __nv_bfloat16* __restrict__ klo,
               __nv_bfloat16* __restrict__ vhi, __nv_bfloat16* __restrict__ vlo,
               const float* __restrict__ cstab, const float* __restrict__ sntab) {
    extern __shared__ char dynsm[];
    const uint32_t sb = smem_u32(dynsm);
    const int tid = threadIdx.x;
    const int lane = tid & 31, wid = tid >> 5;
    const int warpM = (wid & 1) * 64;    // 0 or 64
    const int warpN = (wid >> 1) * 64;   // 0..192
    const int m0 = blockIdx.y * 128;
    const int n0 = blockIdx.x * 256;
    const int nk = K / 32;

    const __nv_bfloat16* Asrc[2] = { Ahi + (size_t)m0 * K, Alo + (size_t)m0 * K };
    const __nv_bfloat16* Bsrc[2] = { Bhi + (size_t)n0 * K, Blo + (size_t)n0 * K };

    auto load_stage = [&](int stage, int kc) {
        const int k0 = kc * 32;
        const uint32_t dbase = sb + stage * STG_B;
        #pragma unroll
        for (int j = 0; j < 12; j++) {
            int idx = tid + 256 * j;           // 0..3071
            int rg = idx >> 2;                 // 0..767
            int ch = idx & 3;
            uint32_t dst;
            const __nv_bfloat16* src;
            if (rg < 256) {
                int arr = rg >> 7, row = rg & 127;
                src = Asrc[arr] + (size_t)row * K + k0 + ch * 8;
                dst = dbase + arr * A_B + row * ROWB + ch * 16;
            } else {
                int rgb = rg - 256;
                int arr = rgb >> 8, row = rgb & 255;
                src = Bsrc[arr] + (size_t)row * K + k0 + ch * 8;
                dst = dbase + 2 * A_B + arr * B_B + row * ROWB + ch * 16;
            }
            cp_async16(dst, src);
        }
        CP_COMMIT();
    };

    const uint32_t aoff = (uint32_t)(warpM + (lane & 15)) * ROWB + (lane >> 4) * 16;
    const uint32_t boff = (uint32_t)(warpN + (lane >> 4) * 8 + (lane & 7)) * ROWB
                          + ((lane >> 3) & 1) * 16;

    float acc[4][8][4] = {};

    load_stage(0, 0);

    for (int kc = 0; kc < nk; kc++) {
        if (kc + 1 < nk) {
            load_stage((kc + 1) & 1, kc + 1);
            CP_WAIT1();
        } else {
            CP_WAIT0();
        }
        __syncthreads();

        const uint32_t stb = sb + (kc & 1) * STG_B;
        #pragma unroll
        for (int ks = 0; ks < 2; ks++) {
            const uint32_t ko = ks * 32;
            uint32_t ah[4][4], al[4][4];
            #pragma unroll
            for (int mt = 0; mt < 4; mt++) {
                uint32_t a = stb + aoff + mt * (16 * ROWB) + ko;
                ldsm4(ah[mt], a);
                ldsm4(al[mt], a + A_B);
            }
            #pragma unroll
            for (int p = 0; p < 4; p++) {
                uint32_t bh[4], bl[4];
                uint32_t b = stb + 2 * A_B + boff + p * (16 * ROWB) + ko;
                ldsm4(bh, b);
                ldsm4(bl, b + B_B);
                #pragma unroll
                for (int mt = 0; mt < 4; mt++) {
                    #pragma unroll
                    for (int half = 0; half < 2; half++) {
                        float* c = acc[mt][2 * p + half];
                        mma_bf16(c, ah[mt], &bh[half * 2]);
                        mma_bf16(c, ah[mt], &bl[half * 2]);
                        mma_bf16(c, al[mt], &bh[half * 2]);
                    }
                }
            }
        }
        __syncthreads();
    }

    const int frow = lane >> 2;
    const int fcol = (lane & 3) * 2;

    if (EPI == 2) {
        // ---- fused uvqk epilogue ----
        const int gcol0 = n0 + warpN;              // head-aligned (64)
        const int region = gcol0 >> 10;            // 0=u 1=v 2=q 3=k
        const int hh = (gcol0 & 1023) >> 6;        // head index
        #pragma unroll
        for (int mt = 0; mt < 4; mt++) {
            const int mr0 = m0 + warpM + mt * 16 + frow;
            const int mr1 = mr0 + 8;
            const int b0 = mr0 >> 11, s0 = mr0 & (SS - 1);
            const int b1 = mr1 >> 11, s1 = mr1 & (SS - 1);
            const size_t ob0 = ((size_t)(b0 * HH + hh) * SS + s0) * HD;
            const size_t ob1 = ((size_t)(b1 * HH + hh) * SS + s1) * HD;
            if (region == 0) {
                #pragma unroll
                for (int nt = 0; nt < 8; nt++) {
                    const int n = gcol0 + nt * 8 + fcol;
                    const float* a = acc[mt][nt];
                    float2 bv = *reinterpret_cast<const float2*>(bias + n);
                    float x0 = a[0] + bv.x, y0 = a[1] + bv.y;
                    float x1 = a[2] + bv.x, y1 = a[3] + bv.y;
                    x0 = x0 / (1.0f + __expf(-x0));
                    y0 = y0 / (1.0f + __expf(-y0));
                    x1 = x1 / (1.0f + __expf(-x1));
                    y1 = y1 / (1.0f + __expf(-y1));
                    *reinterpret_cast<float2*>(u + (size_t)mr0 * DD + n) = make_float2(x0, y0);
                    *reinterpret_cast<float2*>(u + (size_t)mr1 * DD + n) = make_float2(x1, y1);
                }
            } else if (region == 1) {
                #pragma unroll
                for (int nt = 0; nt < 8; nt++) {
                    const int d0 = nt * 8 + fcol;
                    const int n = gcol0 + d0;
                    const float* a = acc[mt][nt];
                    float2 bv = *reinterpret_cast<const float2*>(bias + n);
                    split_store2(vhi, vlo, ob0 + d0, a[0] + bv.x, a[1] + bv.y);
                    split_store2(vhi, vlo, ob1 + d0, a[2] + bv.x, a[3] + bv.y);
                }
            } else {
                __nv_bfloat16* dhi = (region == 2) ? qhi : khi;
                __nv_bfloat16* dlo = (region == 2) ? qlo : klo;
                #pragma unroll
                for (int nt = 0; nt < 4; nt++) {
                    const int d0 = nt * 8 + fcol;          // 0..30
                    const int n = gcol0 + d0;
                    const float* a1 = acc[mt][nt];         // cols d0, d0+1
                    const float* a2 = acc[mt][nt + 4];     // cols d0+32, d0+33
                    float2 bv1 = *reinterpret_cast<const float2*>(bias + n);
                    float2 bv2 = *reinterpret_cast<const float2*>(bias + n + 32);
                    // row mr0
                    {
                        float2 c2 = *reinterpret_cast<const float2*>(cstab + (size_t)mr0 * 32 + d0);
                        float2 s2 = *reinterpret_cast<const float2*>(sntab + (size_t)mr0 * 32 + d0);
                        float q1a = a1[0] + bv1.x, q1b = a1[1] + bv1.y;
                        float q2a = a2[0] + bv2.x, q2b = a2[1] + bv2.y;
                        split_store2(dhi, dlo, ob0 + d0,
                                     q1a * c2.x - q2a * s2.x, q1b * c2.y - q2b * s2.y);
                        split_store2(dhi, dlo, ob0 + d0 + 32,
                                     q2a * c2.x + q1a * s2.x, q2b * c2.y + q1b * s2.y);
                    }
                    // row mr1
                    {
                        float2 c2 = *reinterpret_cast<const float2*>(cstab + (size_t)mr1 * 32 + d0);
                        float2 s2 = *reinterpret_cast<const float2*>(sntab + (size_t)mr1 * 32 + d0);
                        float q1a = a1[2] + bv1.x, q1b = a1[3] + bv1.y;
                        float q2a = a2[2] + bv2.x, q2b = a2[3] + bv2.y;
                        split_store2(dhi, dlo, ob1 + d0,
                                     q1a * c2.x - q2a * s2.x, q1b * c2.y - q2b * s2.y);
                        split_store2(dhi, dlo, ob1 + d0 + 32,
                                     q2a * c2.x + q1a * s2.x, q2b * c2.y + q1b * s2.y);
                    }
                }
            }
        }
    } else {
        // ---- out-proj epilogue: C = acc + bias + res (+ optional split) ----
        #pragma unroll
        for (int mt = 0; mt < 4; mt++) {
            const int m = m0 + warpM + mt * 16 + frow;
            #pragma unroll
            for (int nt = 0; nt < 8; nt++) {
                const int n = n0 + warpN + nt * 8 + fcol;
                const float* a = acc[mt][nt];
                float2 bv = *reinterpret_cast<const float2*>(bias + n);
                float2 r0 = *reinterpret_cast<const float2*>(res + (size_t)m * N + n);
                float2 r1 = *reinterpret_cast<const float2*>(res + (size_t)(m + 8) * N + n);
                float2 o0 = { a[0] + bv.x + r0.x, a[1] + bv.y + r0.y };
                float2 o1 = { a[2] + bv.x + r1.x, a[3] + bv.y + r1.y };
                *reinterpret_cast<float2*>(C + (size_t)m * N + n) = o0;
                *reinterpret_cast<float2*>(C + (size_t)(m + 8) * N + n) = o1;
                if (EPI == 1) {
                    split_store2(Chi, Clo, (size_t)m * N + n, o0.x, o0.y);
                    split_store2(Chi, Clo, (size_t)(m + 8) * N + n, o1.x, o1.y);
                }
            }
        }
    }
}

// ---------------------------------------------------------------------------
// block reduce (256 threads)
// ---------------------------------------------------------------------------
__device__ __forceinline__ float blockReduceSum(float v) {
    __shared__ float red[8];
    int lane = threadIdx.x & 31, wid = threadIdx.x >> 5;
    #pragma unroll
    for (int o = 16; o; o >>= 1) v += __shfl_down_sync(0xFFFFFFFFu, v, o);
    if (lane == 0) red[wid] = v;
    __syncthreads();
    float r = 0.f;
    if (threadIdx.x < 8) r = red[threadIdx.x];
    if (wid == 0) {
        #pragma unroll
        for (int o = 4; o; o >>= 1) r += __shfl_down_sync(0xFFFFFFFFu, r, o);
        if (lane == 0) red[0] = r;
    }
    __syncthreads();
    return red[0];
}

// RMS norm, vectorized: one row per 256-thread block (4 elems/thread).
template<bool SPLIT>
__global__ void rmsnorm_k(const float* __restrict__ in, const float* __restrict__ w,
                          float* __restrict__ out,
                          __nv_bfloat16* __restrict__ ohi, __nv_bfloat16* __restrict__ olo) {
    const int row = blockIdx.x, t = threadIdx.x;
    const size_t off = (size_t)row * DD + t * 4;
    float4 v = *reinterpret_cast<const float4*>(in + off);
    float ss = v.x * v.x + v.y * v.y + v.z * v.z + v.w * v.w;
    float tot = blockReduceSum(ss);
    float inv = rsqrtf(tot / (float)DD + 1e-6f);
    float4 wv = *reinterpret_cast<const float4*>(w + t * 4);
    float4 y = { v.x * wv.x * inv, v.y * wv.y * inv, v.z * wv.z * inv, v.w * wv.w * inv };
    *reinterpret_cast<float4*>(out + off) = y;
    if (SPLIT) {
        split_store2(ohi, olo, off, y.x, y.y);
        split_store2(ohi, olo, off + 2, y.z, y.w);
    }
}

// gated = rms_norm(attn, gate_w) * u  -> bf16 hi/lo split only (vectorized)
__global__ void rmsgate_k(const float* __restrict__ attn, const float* __restrict__ gw,
                          const float* __restrict__ u,
                          __nv_bfloat16* __restrict__ ghi, __nv_bfloat16* __restrict__ glo) {
    const int row = blockIdx.x, t = threadIdx.x;
    const size_t off = (size_t)row * DD + t * 4;
    float4 v = *reinterpret_cast<const float4*>(attn + off);
    float ss = v.x * v.x + v.y * v.y + v.z * v.z + v.w * v.w;
    float tot = blockReduceSum(ss);
    float inv = rsqrtf(tot / (float)DD + 1e-6f);
    float4 wv = *reinterpret_cast<const float4*>(gw + t * 4);
    float4 uv = *reinterpret_cast<const float4*>(u + off);
    float y0 = v.x * wv.x * inv * uv.x;
    float y1 = v.y * wv.y * inv * uv.y;
    float y2 = v.z * wv.z * inv * uv.z;
    float y3 = v.w * wv.w * inv * uv.w;
    split_store2(ghi, glo, off, y0, y1);
    split_store2(ghi, glo, off + 2, y2, y3);
}

// ---------------------------------------------------------------------------
// Tensor-core causal SiLU attention, bf16x3.
// grid=(S/128, B*H), 256 threads (8 warps x 16 q-rows).
// Q fragments hoisted to registers. SiLU via tanh.approx (1 MUFU/elem).
// W split via bit-truncation + byte_perm packing. qt reversed for balance.
// ---------------------------------------------------------------------------
#define AROWB 144                 // 72 elems * 2B, 16B-aligned
#define QA (128 * AROWB)          // 18432 B per Q array
#define KVA (64 * AROWB)          // 9216 B per KV array
#define KVSTG (4 * KVA)           // 36864 B per stage (khi,klo,vhi,vlo)
#define ATTN_SMEM (2 * QA + 3 * KVSTG)   // 147456 B

__global__ __launch_bounds__(256, 1)
void attn_mma_k(const __nv_bfloat16* __restrict__ qhi, const __nv_bfloat16* __restrict__ qlo,
                const __nv_bfloat16* __restrict__ khi, const __nv_bfloat16* __restrict__ klo,
                const __nv_bfloat16* __restrict__ vhi, const __nv_bfloat16* __restrict__ vlo,
                float* __restrict__ out) {
    extern __shared__ char dynsm[];
    const uint32_t sb = smem_u32(dynsm);
    const int tid = threadIdx.x;
    const int lane = tid & 31, wid = tid >> 5;
    const int qt = gridDim.x - 1 - blockIdx.x;    // heavy tiles first
    const int bh = blockIdx.y;
    const int b = bh >> 4, h = bh & 15;
    const int q0 = qt * 128;
    const int nkt = 2 * qt + 2;

    const size_t hb = (size_t)bh * SS;

    // ---- load Q (hi/lo) ----
    {
        const __nv_bfloat16* qsrc[2] = { qhi + (hb + q0) * HD, qlo + (hb + q0) * HD };
        #pragma unroll
        for (int j = 0; j < 8; j++) {
            int idx = tid + 256 * j;
            int arr = idx >> 10, rem = idx & 1023;
            int row = rem >> 3, seg = rem & 7;
            cp_async16(sb + arr * QA + row * AROWB + seg * 16,
                       qsrc[arr] + (size_t)row * HD + seg * 8);
        }
        CP_COMMIT();
    }

    const __nv_bfloat16* kvsrc[4] = { khi + hb * HD, klo + hb * HD,
                                      vhi + hb * HD, vlo + hb * HD };
    auto load_kv = [&](int stage, int kt) {
        const int k0 = kt * 64;
        const uint32_t dbase = sb + 2 * QA + stage * KVSTG;
        #pragma unroll
        for (int j = 0; j < 8; j++) {
            int idx = tid + 256 * j;
            int arr = idx >> 9, rem = idx & 511;
            int row = rem >> 3, seg = rem & 7;
            cp_async16(dbase + arr * KVA + row * AROWB + seg * 16,
                       kvsrc[arr] + (size_t)(k0 + row) * HD + seg * 8);
        }
        CP_COMMIT();
    };

    load_kv(0, 0);
    load_kv(1, 1);

    const uint32_t aoff = (uint32_t)(wid * 16 + (lane & 15)) * AROWB + (lane >> 4) * 16;
    const uint32_t boff = (uint32_t)((lane >> 4) * 8 + (lane & 7)) * AROWB + ((lane >> 3) & 1) * 16;
    const uint32_t voff = (uint32_t)(((lane >> 3) & 1) * 8 + (lane & 7)) * AROWB + (lane >> 4) * 16;

    // ---- hoist Q fragments into registers (reused across all kt tiles) ----
    uint32_t qH[4][4], qL[4][4];
    {
        CP_WAIT2();          // Q group complete (kv0, kv1 may be pending)
        __syncthreads();
        #pragma unroll
        for (int ks = 0; ks < 4; ks++) {
            ldsm4(qH[ks], sb + aoff + ks * 32);
            ldsm4(qL[ks], sb + QA + aoff + ks * 32);
        }
    }

    const int rbase = q0 + wid * 16 + (lane >> 2);
    float o[8][4] = {};

    for (int kt = 0; kt < nkt; kt++) {
        if (kt + 1 < nkt) { CP_WAIT1(); } else { CP_WAIT0(); }
        __syncthreads();

        const int k0 = kt * 64;
        const uint32_t kb = sb + 2 * QA + (kt % 3) * KVSTG;

        if (k0 <= q0 + wid * 16 + 15) {
            // ---- S = Q K^T (bf16x3, Q from registers) ----
            float s[8][4] = {};
            #pragma unroll
            for (int ks = 0; ks < 4; ks++) {
                #pragma unroll
                for (int p = 0; p < 4; p++) {
                    uint32_t bH[4], bL[4];
                    uint32_t ba = kb + boff + p * (16 * AROWB) + ks * 32;
                    ldsm4(bH, ba);
                    ldsm4(bL, ba + KVA);
                    #pragma unroll
                    for (int half = 0; half < 2; half++) {
                        float* acc = s[2 * p + half];
                        mma_bf16(acc, qH[ks], &bH[half * 2]);
                        mma_bf16(acc, qH[ks], &bL[half * 2]);
                        mma_bf16(acc, qL[ks], &bH[half * 2]);
                    }
                }
            }
            // ---- silu (tanh form) + causal mask ----
            // silu(x) = a + a*tanh(a), a = x/2; x = s*0.125 -> a = s*0.0625
            const bool needmask = (k0 + 63 > q0 + wid * 16);
            #pragma unroll
            for (int n = 0; n < 8; n++) {
                int col0 = k0 + 8 * n + (lane & 3) * 2;
                #pragma unroll
                for (int e = 0; e < 4; e++) {
                    int r = rbase + ((e >> 1) ? 8 : 0);
                    int c = col0 + (e & 1);
                    float a = s[n][e] * 0.0625f;
                    float v = fmaf(a, fast_tanh(a), a);
                    if (needmask && c > r) v = 0.0f;
                    s[n][e] = v;
                }
            }
            // ---- O += W V (bf16x3; W split by truncation, hi packed via PRMT) ----
            #pragma unroll
            for (int kk = 0; kk < 4; kk++) {
                const float* t0 = s[2 * kk];
                const float* t1 = s[2 * kk + 1];
                uint32_t u00 = __float_as_uint(t0[0]), u01 = __float_as_uint(t0[1]);
                uint32_t u02 = __float_as_uint(t0[2]), u03 = __float_as_uint(t0[3]);
                uint32_t u10 = __float_as_uint(t1[0]), u11 = __float_as_uint(t1[1]);
                uint32_t u12 = __float_as_uint(t1[2]), u13 = __float_as_uint(t1[3]);
                uint32_t wh[4], wl[4];
                wh[0] = __byte_perm(u00, u01, 0x7632);
                wh[1] = __byte_perm(u02, u03, 0x7632);
                wh[2] = __byte_perm(u10, u11, 0x7632);
                wh[3] = __byte_perm(u12, u13, 0x7632);
                wl[0] = packbf(t0[0] - __uint_as_float(u00 & 0xFFFF0000u),
                               t0[1] - __uint_as_float(u01 & 0xFFFF0000u));
                wl[1] = packbf(t0[2] - __uint_as_float(u02 & 0xFFFF0000u),
                               t0[3] - __uint_as_float(u03 & 0xFFFF0000u));
                wl[2] = packbf(t1[0] - __uint_as_float(u10 & 0xFFFF0000u),
                               t1[1] - __uint_as_float(u11 & 0xFFFF0000u));
                wl[3] = packbf(t1[2] - __uint_as_float(u12 & 0xFFFF0000u),
                               t1[3] - __uint_as_float(u13 & 0xFFFF0000u));
                #pragma unroll
                for (int dg = 0; dg < 4; dg++) {
                    uint32_t va = kb + 2 * KVA + kk * (16 * AROWB) + voff + dg * 32;
                    uint32_t vH[4], vL[4];
                    ldsm4t(vH, va);
                    ldsm4t(vL, va + KVA);
                    #pragma unroll
                    for (int half = 0; half < 2; half++) {
                        float* acc = o[2 * dg + half];
                        mma_bf16(acc, wh, &vH[half * 2]);
                        mma_bf16(acc, wh, &vL[half * 2]);
                        mma_bf16(acc, wl, &vH[half * 2]);
                    }
                }
            }
        }

        if (kt + 2 < nkt) load_kv((kt + 2) % 3, kt + 2);
    }

    const int row0 = q0 + wid * 16 + (lane >> 2);
    #pragma unroll
    for (int dt = 0; dt < 8; dt++) {
        int col = h * HD + dt * 8 + (lane & 3) * 2;
        *reinterpret_cast<float2*>(out + (size_t)(b * SS + row0) * DD + col) =
            make_float2(o[dt][0], o[dt][1]);
        *reinterpret_cast<float2*>(out + (size_t)(b * SS + row0 + 8) * DD + col) =
            make_float2(o[dt][2], o[dt][3]);
    }
}

// ---------------------------------------------------------------------------
// kernel_launch
// ---------------------------------------------------------------------------
extern "C" void kernel_launch(void* const* d_in, const int* in_sizes, int n_in,
                              void* d_out, int out_size) {
    const float* x        = (const float*)d_in[0];
    const float* td       = (const float*)d_in[1];
    // d_in[2] = attn_mask: structurally tril(ones) -> causal mask applied in-kernel
    const float* uvqk_w   = (const float*)d_in[3];
    const float* uvqk_b   = (const float*)d_in[4];
    const float* gate_w   = (const float*)d_in[5];
    const float* out_w    = (const float*)d_in[6];
    const float* out_b    = (const float*)d_in[7];
    const float* in_nw    = (const float*)d_in[8];
    const float* last_nw  = (const float*)d_in[9];
    const int*   pos_ids  = (const int*)d_in[10];
    float* out = (float*)d_out;

    void *ph, *pu, *pattn, *pcs, *psn;
    void *pwqh, *pwql, *pwoh, *pwol, *pahi, *palo, *pghi, *pglo;
    void *pqh, *pql, *pkh, *pkl, *pvh, *pvl;
    cudaGetSymbolAddress(&ph, g_h);
    cudaGetSymbolAddress(&pu, g_u);
    cudaGetSymbolAddress(&pattn, g_attn);
    cudaGetSymbolAddress(&pcs, g_cs);
    cudaGetSymbolAddress(&psn, g_sn);
    cudaGetSymbolAddress(&pwqh, g_wqk_hi);
    cudaGetSymbolAddress(&pwql, g_wqk_lo);
    cudaGetSymbolAddress(&pwoh, g_wo_hi);
    cudaGetSymbolAddress(&pwol, g_wo_lo);
    cudaGetSymbolAddress(&pahi, g_ahi);
    cudaGetSymbolAddress(&palo, g_alo);
    cudaGetSymbolAddress(&pghi, g_ghi);
    cudaGetSymbolAddress(&pglo, g_glo);
    cudaGetSymbolAddress(&pqh, g_qhi);
    cudaGetSymbolAddress(&pql, g_qlo);
    cudaGetSymbolAddress(&pkh, g_khi);
    cudaGetSymbolAddress(&pkl, g_klo);
    cudaGetSymbolAddress(&pvh, g_vhi);
    cudaGetSymbolAddress(&pvl, g_vlo);
    float* h    = (float*)ph;
    float* u    = (float*)pu;
    float* attn = (float*)pattn;
    float* cs   = (float*)pcs;
    float* sn   = (float*)psn;
    __nv_bfloat16* wqh = (__nv_bfloat16*)pwqh;
    __nv_bfloat16* wql = (__nv_bfloat16*)pwql;
    __nv_bfloat16* woh = (__nv_bfloat16*)pwoh;
    __nv_bfloat16* wol = (__nv_bfloat16*)pwol;
    __nv_bfloat16* ahi = (__nv_bfloat16*)pahi;
    __nv_bfloat16* alo = (__nv_bfloat16*)palo;
    __nv_bfloat16* ghi = (__nv_bfloat16*)pghi;
    __nv_bfloat16* glo = (__nv_bfloat16*)pglo;
    __nv_bfloat16* qhi = (__nv_bfloat16*)pqh;
    __nv_bfloat16* qlo = (__nv_bfloat16*)pql;
    __nv_bfloat16* khi = (__nv_bfloat16*)pkh;
    __nv_bfloat16* klo = (__nv_bfloat16*)pkl;
    __nv_bfloat16* vhi = (__nv_bfloat16*)pvh;
    __nv_bfloat16* vlo = (__nv_bfloat16*)pvl;

    cudaFuncSetAttribute(attn_mma_k, cudaFuncAttributeMaxDynamicSharedMemorySize, ATTN_SMEM);
    cudaFuncSetAttribute(mmagemm_k<0>, cudaFuncAttributeMaxDynamicSharedMemorySize, GSMEM);
    cudaFuncSetAttribute(mmagemm_k<1>, cudaFuncAttributeMaxDynamicSharedMemorySize, GSMEM);
    cudaFuncSetAttribute(mmagemm_k<2>, cudaFuncAttributeMaxDynamicSharedMemorySize, GSMEM);

    // one-time: weight convert + rope table
    wconv_k<<<dim3(FOURD / 32, DD / 32, LL), dim3(32, 8)>>>(uvqk_w, wqh, wql, DD, FOURD);
    wconv_k<<<dim3(DD / 32, DD / 32, LL), dim3(32, 8)>>>(out_w, woh, wol, DD, DD);
    costab_k<<<(MROWS * 32) / 256, 256>>>(td, pos_ids, cs, sn);

    // h = rms_norm(x, in_norm_w), plus bf16 split into ahi/alo
    rmsnorm_k<true><<<MROWS, 256>>>(x, in_nw, h, ahi, alo);

    for (int l = 0; l < LL; l++) {
        const __nv_bfloat16* wqhl = wqh + (size_t)l * FOURD * DD;
        const __nv_bfloat16* wqll = wql + (size_t)l * FOURD * DD;
        const __nv_bfloat16* wohl = woh + (size_t)l * DD * DD;
        const __nv_bfloat16* woll = wol + (size_t)l * DD * DD;
        const float* bl  = uvqk_b + (size_t)l * FOURD;
        const float* gwl = gate_w + (size_t)l * DD;
        const float* obl = out_b + (size_t)l * DD;

        // uvqk GEMM with fused silu/rope/split epilogue
        mmagemm_k<2><<<dim3(FOURD / 256, MROWS / 128), 256, GSMEM>>>(
            FOURD, DD, ahi, alo, wqhl, wqll, bl, nullptr, nullptr, nullptr, nullptr,
            u, qhi, qlo, khi, klo, vhi, vlo, cs, sn);
        // attention (tensor cores)
        attn_mma_k<<<dim3(SS / 128, BB * HH), 256, ATTN_SMEM>>>(
            qhi, qlo, khi, klo, vhi, vlo, attn);
        // gated = rms_norm(attn, gate_w) * u -> split
        rmsgate_k<<<MROWS, 256>>>(attn, gwl, u, ghi, glo);
        // h = h + g @ out_w + out_b; split h for next layer's GEMM
        if (l + 1 < LL) {
            mmagemm_k<1><<<dim3(DD / 256, MROWS / 128), 256, GSMEM>>>(
                DD, DD, ghi, glo, wohl, woll, obl, h, h, ahi, alo,
                nullptr, nullptr, nullptr, nullptr, nullptr, nullptr, nullptr,
                nullptr, nullptr);
        } else {
            mmagemm_k<0><<<dim3(DD / 256, MROWS / 128), 256, GSMEM>>>(
                DD, DD, ghi, glo, wohl, woll, obl, h, h, nullptr, nullptr,
                nullptr, nullptr, nullptr, nullptr, nullptr, nullptr, nullptr,
                nullptr, nullptr);
        }
    }

    rmsnorm_k<false><<<MROWS, 256>>>(h, last_nw, out, nullptr, nullptr);
}